// round 8
// baseline (speedup 1.0000x reference)
#include <cuda_runtime.h>
#include <cuda_fp16.h>
#include <cstdint>

// Problem constants
#define BB 8
#define SEQ 1024
#define CC 512
#define NH 8
#define HD 64
#define NG 32
#define GSZ 16
#define C3 1536

// Scratch
__device__ __half g_xn_h[BB * SEQ * CC];    // normalized x (fp16)
__device__ __half g_qkv_h[BB * SEQ * C3];   // qkv projection (fp16)
__device__ __half g_attn_h[BB * SEQ * CC];  // attention output (fp16)
__device__ __half g_wth_qkv[C3 * CC];       // w_qkv^T [N,K] fp16
__device__ __half g_wth_out[CC * CC];       // w_out^T [N,K] fp16

// ---------------------------------------------------------------------------
// helpers
// ---------------------------------------------------------------------------
__device__ __forceinline__ uint32_t smem_u32(const void* p) {
    uint32_t a; asm("{ .reg .u64 t; cvta.to.shared.u64 t, %1; cvt.u32.u64 %0, t; }" : "=r"(a) : "l"(p));
    return a;
}
__device__ __forceinline__ uint32_t f22u(float a, float b) {
    __half2 h = __floats2half2_rn(a, b);
    return *reinterpret_cast<uint32_t*>(&h);
}

#define CP_ASYNC16(sa, ga) \
    asm volatile("cp.async.cg.shared.global [%0], [%1], 16;" :: "r"(sa), "l"(ga))
#define CP_COMMIT() asm volatile("cp.async.commit_group;")
#define CP_WAIT(n)  asm volatile("cp.async.wait_group %0;" :: "n"(n))

#define LDMATRIX_X4(r0, r1, r2, r3, addr) \
    asm volatile("ldmatrix.sync.aligned.m8n8.x4.shared.b16 {%0,%1,%2,%3}, [%4];" \
        : "=r"(r0), "=r"(r1), "=r"(r2), "=r"(r3) : "r"(addr))

#define LDMATRIX_X4_T(r0, r1, r2, r3, addr) \
    asm volatile("ldmatrix.sync.aligned.m8n8.x4.trans.shared.b16 {%0,%1,%2,%3}, [%4];" \
        : "=r"(r0), "=r"(r1), "=r"(r2), "=r"(r3) : "r"(addr))

#define MMA16816(c, a0, a1, a2, a3, b0, b1) \
    asm volatile("mma.sync.aligned.m16n8k16.row.col.f32.f16.f16.f32 " \
        "{%0,%1,%2,%3}, {%4,%5,%6,%7}, {%8,%9}, {%0,%1,%2,%3};" \
        : "+f"((c)[0]), "+f"((c)[1]), "+f"((c)[2]), "+f"((c)[3]) \
        : "r"(a0), "r"(a1), "r"(a2), "r"(a3), "r"(b0), "r"(b1))

// ---------------------------------------------------------------------------
// Kernel 0: weight transpose + fp16 convert. W[512,N] -> Wt[N,512] (half)
// ---------------------------------------------------------------------------
__global__ __launch_bounds__(256) void wt_kernel(
    const float* __restrict__ W, __half* __restrict__ Wt, int N)
{
    __shared__ float t[32][33];
    int kb = blockIdx.y * 32, nb = blockIdx.x * 32;
    int tx = threadIdx.x, ty = threadIdx.y;   // 32 x 8
    #pragma unroll
    for (int i = 0; i < 32; i += 8)
        t[ty + i][tx] = W[(size_t)(kb + ty + i) * N + nb + tx];
    __syncthreads();
    #pragma unroll
    for (int i = 0; i < 32; i += 8)
        Wt[(size_t)(nb + ty + i) * 512 + kb + tx] = __float2half_rn(t[tx][ty + i]);
}

// ---------------------------------------------------------------------------
// Kernel 1: GroupNorm -> fp16 output
// ---------------------------------------------------------------------------
__global__ __launch_bounds__(256) void gn_kernel(
    const float* __restrict__ x, const float* __restrict__ gamma,
    const float* __restrict__ beta, __half* __restrict__ xn)
{
    int bg = blockIdx.x;
    int b = bg >> 5, g = bg & 31;
    const float* base = x + (size_t)b * SEQ * CC + g * GSZ;
    int tid = threadIdx.x;

    float sum = 0.f, sq = 0.f;
    #pragma unroll
    for (int i = 0; i < 4; i++) {
        int s = tid + i * 256;
        const float4* p = reinterpret_cast<const float4*>(base + (size_t)s * CC);
        #pragma unroll
        for (int v4 = 0; v4 < 4; v4++) {
            float4 v = p[v4];
            sum += v.x + v.y + v.z + v.w;
            sq  += v.x * v.x + v.y * v.y + v.z * v.z + v.w * v.w;
        }
    }
    #pragma unroll
    for (int off = 16; off; off >>= 1) {
        sum += __shfl_xor_sync(0xFFFFFFFFu, sum, off);
        sq  += __shfl_xor_sync(0xFFFFFFFFu, sq, off);
    }
    __shared__ float red[2][8];
    __shared__ float stats[2];
    int wid = tid >> 5, lid = tid & 31;
    if (lid == 0) { red[0][wid] = sum; red[1][wid] = sq; }
    __syncthreads();
    if (tid == 0) {
        float S = 0.f, Q = 0.f;
        #pragma unroll
        for (int w = 0; w < 8; w++) { S += red[0][w]; Q += red[1][w]; }
        float mu = S * (1.f / 16384.f);
        float var = Q * (1.f / 16384.f) - mu * mu;
        stats[0] = mu;
        stats[1] = rsqrtf(var + 1e-6f);
    }
    __syncthreads();
    float mu = stats[0], rstd = stats[1];

    float ga[GSZ], be[GSZ];
    #pragma unroll
    for (int c = 0; c < GSZ; c++) {
        ga[c] = gamma[g * GSZ + c] * rstd;
        be[c] = beta[g * GSZ + c];
    }
    __half* obase = xn + (size_t)b * SEQ * CC + g * GSZ;
    #pragma unroll
    for (int i = 0; i < 4; i++) {
        int s = tid + i * 256;
        const float4* p = reinterpret_cast<const float4*>(base + (size_t)s * CC);
        __half2* q = reinterpret_cast<__half2*>(obase + (size_t)s * CC);
        #pragma unroll
        for (int v4 = 0; v4 < 4; v4++) {
            float4 v = p[v4];
            int c = v4 * 4;
            float y0 = (v.x - mu) * ga[c + 0] + be[c + 0];
            float y1 = (v.y - mu) * ga[c + 1] + be[c + 1];
            float y2 = (v.z - mu) * ga[c + 2] + be[c + 2];
            float y3 = (v.w - mu) * ga[c + 3] + be[c + 3];
            q[v4 * 2 + 0] = __floats2half2_rn(y0, y1);
            q[v4 * 2 + 1] = __floats2half2_rn(y2, y3);
        }
    }
}

// ---------------------------------------------------------------------------
// Kernel 2: fp16 HMMA GEMM, 4-stage cp.async pipeline, 1 barrier/stage.
// C[M,N] = A[M,512](h) @ Wt[N,512](h)^T + bias (+R)
// CTA 128x128, BK=32, 8 warps, warp tile 32x64. Dynamic smem 80KB.
// ---------------------------------------------------------------------------
#define GSTRIDE 40
#define GSLOT (128 * GSTRIDE)

template<bool HOUT>
__global__ __launch_bounds__(256) void gemm_hmma(
    const __half* __restrict__ A, const __half* __restrict__ Wt,
    const float* __restrict__ bias, const float* __restrict__ R,
    void* __restrict__ Cv, int N)
{
    extern __shared__ __half dsm[];
    __half* AsB = dsm;              // [4][GSLOT]
    __half* BsB = dsm + 4 * GSLOT;  // [4][GSLOT]

    int tid = threadIdx.x;
    int lane = tid & 31;
    int wid = tid >> 5;
    int wm = (wid & 3) * 32;
    int wn = (wid >> 2) * 64;
    int bm = blockIdx.y * 128;
    int bn = blockIdx.x * 128;

    float c[2][8][4];
    #pragma unroll
    for (int mi = 0; mi < 2; mi++)
        #pragma unroll
        for (int ni = 0; ni < 8; ni++)
            #pragma unroll
            for (int k = 0; k < 4; k++) c[mi][ni][k] = 0.f;

    auto stage = [&](int s, int slot) {
        const __half* Ag = A + (size_t)bm * 512 + s * 32;
        const __half* Bg = Wt + (size_t)bn * 512 + s * 32;
        __half* Ad = AsB + slot * GSLOT;
        __half* Bd = BsB + slot * GSLOT;
        #pragma unroll
        for (int i = 0; i < 2; i++) {
            int chunk = tid + i * 256;
            int r = chunk >> 2, cc = chunk & 3;
            CP_ASYNC16(smem_u32(&Ad[r * GSTRIDE + cc * 8]), Ag + (size_t)r * 512 + cc * 8);
            CP_ASYNC16(smem_u32(&Bd[r * GSTRIDE + cc * 8]), Bg + (size_t)r * 512 + cc * 8);
        }
    };

    stage(0, 0); CP_COMMIT();
    stage(1, 1); CP_COMMIT();
    stage(2, 2); CP_COMMIT();

    for (int s = 0; s < 16; s++) {
        int rem = 15 - s;
        if (rem >= 2)      CP_WAIT(2);
        else if (rem == 1) CP_WAIT(1);
        else               CP_WAIT(0);
        __syncthreads();   // also frees slot (s-1)&3 == (s+3)&3 for staging
        if (s + 3 < 16) { stage(s + 3, (s + 3) & 3); CP_COMMIT(); }

        const __half* Ab = AsB + (s & 3) * GSLOT;
        const __half* Bb = BsB + (s & 3) * GSLOT;
        #pragma unroll
        for (int kk = 0; kk < 2; kk++) {
            uint32_t a[2][4];
            #pragma unroll
            for (int mi = 0; mi < 2; mi++) {
                int row = wm + mi * 16 + (lane & 7) + ((lane >> 3) & 1) * 8;
                int kc = kk * 16 + ((lane >> 4) & 1) * 8;
                uint32_t addr = smem_u32(&Ab[row * GSTRIDE + kc]);
                LDMATRIX_X4(a[mi][0], a[mi][1], a[mi][2], a[mi][3], addr);
            }
            uint32_t b[8][2];
            #pragma unroll
            for (int bi = 0; bi < 4; bi++) {
                int n = wn + bi * 16 + (lane & 7) + ((lane >> 4) & 1) * 8;
                int kc = kk * 16 + ((lane >> 3) & 1) * 8;
                uint32_t addr = smem_u32(&Bb[n * GSTRIDE + kc]);
                uint32_t r0, r1, r2, r3;
                LDMATRIX_X4(r0, r1, r2, r3, addr);
                b[bi * 2 + 0][0] = r0; b[bi * 2 + 0][1] = r1;
                b[bi * 2 + 1][0] = r2; b[bi * 2 + 1][1] = r3;
            }
            #pragma unroll
            for (int mi = 0; mi < 2; mi++)
                #pragma unroll
                for (int ni = 0; ni < 8; ni++)
                    MMA16816(c[mi][ni], a[mi][0], a[mi][1], a[mi][2], a[mi][3],
                             b[ni][0], b[ni][1]);
        }
    }

    // epilogue
    #pragma unroll
    for (int mi = 0; mi < 2; mi++) {
        int r0 = bm + wm + mi * 16 + (lane >> 2);
        #pragma unroll
        for (int ni = 0; ni < 8; ni++) {
            int col = bn + wn + ni * 8 + (lane & 3) * 2;
            float bx = bias[col], by = bias[col + 1];
            float v00 = c[mi][ni][0] + bx, v01 = c[mi][ni][1] + by;
            float v10 = c[mi][ni][2] + bx, v11 = c[mi][ni][3] + by;
            if (HOUT) {
                __half* C = (__half*)Cv;
                *reinterpret_cast<__half2*>(C + (size_t)r0 * N + col) = __floats2half2_rn(v00, v01);
                *reinterpret_cast<__half2*>(C + (size_t)(r0 + 8) * N + col) = __floats2half2_rn(v10, v11);
            } else {
                float* C = (float*)Cv;
                if (R) {
                    const float2 ra = *reinterpret_cast<const float2*>(R + (size_t)r0 * N + col);
                    const float2 rb = *reinterpret_cast<const float2*>(R + (size_t)(r0 + 8) * N + col);
                    v00 += ra.x; v01 += ra.y; v10 += rb.x; v11 += rb.y;
                }
                *reinterpret_cast<float2*>(C + (size_t)r0 * N + col) = make_float2(v00, v01);
                *reinterpret_cast<float2*>(C + (size_t)(r0 + 8) * N + col) = make_float2(v10, v11);
            }
        }
    }
}

// ---------------------------------------------------------------------------
// Kernel 3: HMMA flash attention, 3-slot KV ring, 1 barrier/chunk.
// CTA = (b, h, 128 q-rows). 8 warps x 16 rows. Dynamic smem 72KB.
// ---------------------------------------------------------------------------
#define KSTR 72
#define QHALVES (128 * KSTR)        // 9216
#define KVSLOT  (2 * 64 * KSTR)     // K + V per slot = 9216 halves

__global__ __launch_bounds__(256) void attn_hmma(
    const __half* __restrict__ qkv, __half* __restrict__ out)
{
    extern __shared__ __half dsm[];
    __half* Qs = dsm;

    int b = blockIdx.z, h = blockIdx.y, qt = blockIdx.x;
    int tid = threadIdx.x, lane = tid & 31, wid = tid >> 5;

    const __half* base = qkv + (size_t)b * SEQ * C3 + h * HD;

    auto kslot = [&](int slot) -> __half* { return dsm + QHALVES + slot * KVSLOT; };

    auto stageKV = [&](int c, int slot) {
        __half* Kd = kslot(slot);
        __half* Vd = Kd + 64 * KSTR;
        #pragma unroll
        for (int i = 0; i < 2; i++) {
            int chunk = tid + i * 256;
            int r = chunk >> 3, c8 = (chunk & 7) * 8;
            const __half* kg = base + (size_t)(c * 64 + r) * C3 + CC + c8;
            CP_ASYNC16(smem_u32(&Kd[r * KSTR + c8]), kg);
            CP_ASYNC16(smem_u32(&Vd[r * KSTR + c8]), kg + CC);
        }
    };

    // prologue: Q + KV0 in group 0; KV1 in group 1
    #pragma unroll
    for (int i = 0; i < 4; i++) {
        int chunk = tid + i * 256;
        int r = chunk >> 3, c8 = (chunk & 7) * 8;
        CP_ASYNC16(smem_u32(&Qs[r * KSTR + c8]),
                   base + (size_t)(qt * 128 + r) * C3 + c8);
    }
    stageKV(0, 0); CP_COMMIT();
    stageKV(1, 1); CP_COMMIT();

    float o[8][4];
    #pragma unroll
    for (int i = 0; i < 8; i++)
        #pragma unroll
        for (int k = 0; k < 4; k++) o[i][k] = 0.f;
    float mrow0 = -1e30f, mrow1 = -1e30f, lrow0 = 0.f, lrow1 = 0.f;
    uint32_t qf[4][4];

    for (int ch = 0; ch < 16; ch++) {
        if (ch < 15) CP_WAIT(1);
        else         CP_WAIT(0);
        __syncthreads();   // frees slot (ch-1)%3 == (ch+2)%3 for staging
        if (ch + 2 < 16) { stageKV(ch + 2, (ch + 2) % 3); CP_COMMIT(); }

        const __half* Kb = kslot(ch % 3);
        const __half* Vb = Kb + 64 * KSTR;

        if (ch == 0) {
            #pragma unroll
            for (int ks = 0; ks < 4; ks++) {
                int row = wid * 16 + (lane & 7) + ((lane >> 3) & 1) * 8;
                int col = ks * 16 + ((lane >> 4) & 1) * 8;
                uint32_t a = smem_u32(&Qs[row * KSTR + col]);
                LDMATRIX_X4(qf[ks][0], qf[ks][1], qf[ks][2], qf[ks][3], a);
            }
        }

        // ---- S = Q @ K^T  (16 rows x 64 cols per warp) ----
        float sacc[8][4];
        #pragma unroll
        for (int j = 0; j < 8; j++)
            #pragma unroll
            for (int k = 0; k < 4; k++) sacc[j][k] = 0.f;

        #pragma unroll
        for (int j = 0; j < 8; j++) {
            uint32_t kf[8];
            uint32_t a0 = smem_u32(&Kb[(8 * j + (lane & 7)) * KSTR + (lane >> 3) * 8]);
            LDMATRIX_X4(kf[0], kf[1], kf[2], kf[3], a0);
            LDMATRIX_X4(kf[4], kf[5], kf[6], kf[7], a0 + 64);  // +32 halves
            #pragma unroll
            for (int ks = 0; ks < 4; ks++)
                MMA16816(sacc[j], qf[ks][0], qf[ks][1], qf[ks][2], qf[ks][3],
                         kf[2 * ks], kf[2 * ks + 1]);
        }

        // ---- online softmax (scale^2 = 1/64 folded here) ----
        const float sc = 1.0f / 64.0f;
        #pragma unroll
        for (int j = 0; j < 8; j++)
            #pragma unroll
            for (int k = 0; k < 4; k++) sacc[j][k] *= sc;

        float mx0 = mrow0, mx1 = mrow1;
        #pragma unroll
        for (int j = 0; j < 8; j++) {
            mx0 = fmaxf(mx0, fmaxf(sacc[j][0], sacc[j][1]));
            mx1 = fmaxf(mx1, fmaxf(sacc[j][2], sacc[j][3]));
        }
        mx0 = fmaxf(mx0, __shfl_xor_sync(0xFFFFFFFFu, mx0, 1));
        mx0 = fmaxf(mx0, __shfl_xor_sync(0xFFFFFFFFu, mx0, 2));
        mx1 = fmaxf(mx1, __shfl_xor_sync(0xFFFFFFFFu, mx1, 1));
        mx1 = fmaxf(mx1, __shfl_xor_sync(0xFFFFFFFFu, mx1, 2));

        float corr0 = __expf(mrow0 - mx0);
        float corr1 = __expf(mrow1 - mx1);
        mrow0 = mx0; mrow1 = mx1;
        lrow0 *= corr0; lrow1 *= corr1;
        #pragma unroll
        for (int nd = 0; nd < 8; nd++) {
            o[nd][0] *= corr0; o[nd][1] *= corr0;
            o[nd][2] *= corr1; o[nd][3] *= corr1;
        }

        uint32_t pf[4][4];
        #pragma unroll
        for (int jp = 0; jp < 4; jp++) {
            float p00 = __expf(sacc[2 * jp][0] - mx0);
            float p01 = __expf(sacc[2 * jp][1] - mx0);
            float p10 = __expf(sacc[2 * jp][2] - mx1);
            float p11 = __expf(sacc[2 * jp][3] - mx1);
            float p20 = __expf(sacc[2 * jp + 1][0] - mx0);
            float p21 = __expf(sacc[2 * jp + 1][1] - mx0);
            float p30 = __expf(sacc[2 * jp + 1][2] - mx1);
            float p31 = __expf(sacc[2 * jp + 1][3] - mx1);
            lrow0 += p00 + p01 + p20 + p21;
            lrow1 += p10 + p11 + p30 + p31;
            pf[jp][0] = f22u(p00, p01);
            pf[jp][1] = f22u(p10, p11);
            pf[jp][2] = f22u(p20, p21);
            pf[jp][3] = f22u(p30, p31);
        }

        // ---- O += P @ V ----
        #pragma unroll
        for (int ks = 0; ks < 4; ks++) {
            #pragma unroll
            for (int np = 0; np < 4; np++) {
                uint32_t v0, v1, v2, v3;
                int row = 16 * ks + ((lane >> 3) & 1) * 8 + (lane & 7);
                int col = np * 16 + (lane >> 4) * 8;
                LDMATRIX_X4_T(v0, v1, v2, v3, smem_u32(&Vb[row * KSTR + col]));
                MMA16816(o[2 * np], pf[ks][0], pf[ks][1], pf[ks][2], pf[ks][3], v0, v1);
                MMA16816(o[2 * np + 1], pf[ks][0], pf[ks][1], pf[ks][2], pf[ks][3], v2, v3);
            }
        }
    }

    // ---- finalize: reduce l over quad, normalize, store fp16 ----
    lrow0 += __shfl_xor_sync(0xFFFFFFFFu, lrow0, 1);
    lrow0 += __shfl_xor_sync(0xFFFFFFFFu, lrow0, 2);
    lrow1 += __shfl_xor_sync(0xFFFFFFFFu, lrow1, 1);
    lrow1 += __shfl_xor_sync(0xFFFFFFFFu, lrow1, 2);
    float inv0 = 1.0f / lrow0, inv1 = 1.0f / lrow1;

    int r0 = qt * 128 + wid * 16 + (lane >> 2);
    __half* ob = out + (size_t)b * SEQ * CC + h * HD;
    #pragma unroll
    for (int nd = 0; nd < 8; nd++) {
        int col = nd * 8 + (lane & 3) * 2;
        *reinterpret_cast<__half2*>(ob + (size_t)r0 * CC + col) =
            __floats2half2_rn(o[nd][0] * inv0, o[nd][1] * inv0);
        *reinterpret_cast<__half2*>(ob + (size_t)(r0 + 8) * CC + col) =
            __floats2half2_rn(o[nd][2] * inv1, o[nd][3] * inv1);
    }
}

// ---------------------------------------------------------------------------
// Launch
// ---------------------------------------------------------------------------
#define GEMM_SMEM (8 * GSLOT * 2)                 // 81920 bytes
#define ATTN_SMEM ((QHALVES + 3 * KVSLOT) * 2)    // 73728 bytes

extern "C" void kernel_launch(void* const* d_in, const int* in_sizes, int n_in,
                              void* d_out, int out_size)
{
    const float* x        = (const float*)d_in[0];
    const float* gn_scale = (const float*)d_in[1];
    const float* gn_bias  = (const float*)d_in[2];
    const float* w_qkv    = (const float*)d_in[3];
    const float* b_qkv    = (const float*)d_in[4];
    const float* w_out    = (const float*)d_in[5];
    const float* b_out    = (const float*)d_in[6];
    float* out            = (float*)d_out;

    __half* xn;   cudaGetSymbolAddress((void**)&xn,   g_xn_h);
    __half* qkv;  cudaGetSymbolAddress((void**)&qkv,  g_qkv_h);
    __half* attn; cudaGetSymbolAddress((void**)&attn, g_attn_h);
    __half* wtq;  cudaGetSymbolAddress((void**)&wtq,  g_wth_qkv);
    __half* wto;  cudaGetSymbolAddress((void**)&wto,  g_wth_out);

    cudaFuncSetAttribute(gemm_hmma<true>,  cudaFuncAttributeMaxDynamicSharedMemorySize, GEMM_SMEM);
    cudaFuncSetAttribute(gemm_hmma<false>, cudaFuncAttributeMaxDynamicSharedMemorySize, GEMM_SMEM);
    cudaFuncSetAttribute(attn_hmma,        cudaFuncAttributeMaxDynamicSharedMemorySize, ATTN_SMEM);

    // 0) weight transposes (fp16)
    {
        dim3 blk(32, 8);
        wt_kernel<<<dim3(C3 / 32, 16), blk>>>(w_qkv, wtq, C3);
        wt_kernel<<<dim3(CC / 32, 16), blk>>>(w_out, wto, CC);
    }

    // 1) GroupNorm -> fp16
    gn_kernel<<<BB * NG, 256>>>(x, gn_scale, gn_bias, xn);

    // 2) QKV projection (HMMA, fp16 out)
    gemm_hmma<true><<<dim3(C3 / 128, (BB * SEQ) / 128), 256, GEMM_SMEM>>>(xn, wtq, b_qkv, nullptr, qkv, C3);

    // 3) Attention (HMMA flash)
    attn_hmma<<<dim3(SEQ / 128, NH, BB), 256, ATTN_SMEM>>>(qkv, attn);

    // 4) Output projection + bias + residual (HMMA, fp32 out)
    gemm_hmma<false><<<dim3(CC / 128, (BB * SEQ) / 128), 256, GEMM_SMEM>>>(attn, wto, b_out, x, out, CC);
}

// round 10
// speedup vs baseline: 1.0177x; 1.0177x over previous
#include <cuda_runtime.h>
#include <cuda_fp16.h>
#include <cstdint>

// Problem constants
#define BB 8
#define SEQ 1024
#define CC 512
#define NH 8
#define HD 64
#define NG 32
#define GSZ 16
#define C3 1536

// Scratch
__device__ __half g_xn_h[BB * SEQ * CC];    // normalized x (fp16)
__device__ __half g_qkv_h[BB * SEQ * C3];   // qkv projection (fp16)
__device__ __half g_attn_h[BB * SEQ * CC];  // attention output (fp16)
__device__ __half g_wh_qkv[CC * C3];        // w_qkv [K,N] fp16
__device__ __half g_wh_out[CC * CC];        // w_out [K,N] fp16

// ---------------------------------------------------------------------------
// helpers
// ---------------------------------------------------------------------------
__device__ __forceinline__ uint32_t smem_u32(const void* p) {
    uint32_t a; asm("{ .reg .u64 t; cvta.to.shared.u64 t, %1; cvt.u32.u64 %0, t; }" : "=r"(a) : "l"(p));
    return a;
}
__device__ __forceinline__ uint32_t f22u(float a, float b) {
    __half2 h = __floats2half2_rn(a, b);
    return *reinterpret_cast<uint32_t*>(&h);
}

#define CP_ASYNC16(sa, ga) \
    asm volatile("cp.async.cg.shared.global [%0], [%1], 16;" :: "r"(sa), "l"(ga))
#define CP_COMMIT() asm volatile("cp.async.commit_group;")
#define CP_WAIT(n)  asm volatile("cp.async.wait_group %0;" :: "n"(n))

#define LDMATRIX_X4(r0, r1, r2, r3, addr) \
    asm volatile("ldmatrix.sync.aligned.m8n8.x4.shared.b16 {%0,%1,%2,%3}, [%4];" \
        : "=r"(r0), "=r"(r1), "=r"(r2), "=r"(r3) : "r"(addr))

#define LDMATRIX_X4_T(r0, r1, r2, r3, addr) \
    asm volatile("ldmatrix.sync.aligned.m8n8.x4.trans.shared.b16 {%0,%1,%2,%3}, [%4];" \
        : "=r"(r0), "=r"(r1), "=r"(r2), "=r"(r3) : "r"(addr))

#define MMA16816(c, a0, a1, a2, a3, b0, b1) \
    asm volatile("mma.sync.aligned.m16n8k16.row.col.f32.f16.f16.f32 " \
        "{%0,%1,%2,%3}, {%4,%5,%6,%7}, {%8,%9}, {%0,%1,%2,%3};" \
        : "+f"((c)[0]), "+f"((c)[1]), "+f"((c)[2]), "+f"((c)[3]) \
        : "r"(a0), "r"(a1), "r"(a2), "r"(a3), "r"(b0), "r"(b1))

// ---------------------------------------------------------------------------
// Kernel 0: weight convert f32 -> f16 (same [K,N] layout, no transpose)
// ---------------------------------------------------------------------------
__global__ __launch_bounds__(256) void wconv_kernel(
    const float* __restrict__ W, __half* __restrict__ Wh, int n)
{
    int i = (blockIdx.x * 256 + threadIdx.x) * 4;
    if (i < n) {
        float4 v = *reinterpret_cast<const float4*>(W + i);
        __half2* o = reinterpret_cast<__half2*>(Wh + i);
        o[0] = __floats2half2_rn(v.x, v.y);
        o[1] = __floats2half2_rn(v.z, v.w);
    }
}

// ---------------------------------------------------------------------------
// Kernel 1: GroupNorm -> fp16 output
// ---------------------------------------------------------------------------
__global__ __launch_bounds__(256) void gn_kernel(
    const float* __restrict__ x, const float* __restrict__ gamma,
    const float* __restrict__ beta, __half* __restrict__ xn)
{
    int bg = blockIdx.x;
    int b = bg >> 5, g = bg & 31;
    const float* base = x + (size_t)b * SEQ * CC + g * GSZ;
    int tid = threadIdx.x;

    float sum = 0.f, sq = 0.f;
    #pragma unroll
    for (int i = 0; i < 4; i++) {
        int s = tid + i * 256;
        const float4* p = reinterpret_cast<const float4*>(base + (size_t)s * CC);
        #pragma unroll
        for (int v4 = 0; v4 < 4; v4++) {
            float4 v = p[v4];
            sum += v.x + v.y + v.z + v.w;
            sq  += v.x * v.x + v.y * v.y + v.z * v.z + v.w * v.w;
        }
    }
    #pragma unroll
    for (int off = 16; off; off >>= 1) {
        sum += __shfl_xor_sync(0xFFFFFFFFu, sum, off);
        sq  += __shfl_xor_sync(0xFFFFFFFFu, sq, off);
    }
    __shared__ float red[2][8];
    __shared__ float stats[2];
    int wid = tid >> 5, lid = tid & 31;
    if (lid == 0) { red[0][wid] = sum; red[1][wid] = sq; }
    __syncthreads();
    if (tid == 0) {
        float S = 0.f, Q = 0.f;
        #pragma unroll
        for (int w = 0; w < 8; w++) { S += red[0][w]; Q += red[1][w]; }
        float mu = S * (1.f / 16384.f);
        float var = Q * (1.f / 16384.f) - mu * mu;
        stats[0] = mu;
        stats[1] = rsqrtf(var + 1e-6f);
    }
    __syncthreads();
    float mu = stats[0], rstd = stats[1];

    float ga[GSZ], be[GSZ];
    #pragma unroll
    for (int c = 0; c < GSZ; c++) {
        ga[c] = gamma[g * GSZ + c] * rstd;
        be[c] = beta[g * GSZ + c];
    }
    __half* obase = xn + (size_t)b * SEQ * CC + g * GSZ;
    #pragma unroll
    for (int i = 0; i < 4; i++) {
        int s = tid + i * 256;
        const float4* p = reinterpret_cast<const float4*>(base + (size_t)s * CC);
        __half2* q = reinterpret_cast<__half2*>(obase + (size_t)s * CC);
        #pragma unroll
        for (int v4 = 0; v4 < 4; v4++) {
            float4 v = p[v4];
            int c = v4 * 4;
            float y0 = (v.x - mu) * ga[c + 0] + be[c + 0];
            float y1 = (v.y - mu) * ga[c + 1] + be[c + 1];
            float y2 = (v.z - mu) * ga[c + 2] + be[c + 2];
            float y3 = (v.w - mu) * ga[c + 3] + be[c + 3];
            q[v4 * 2 + 0] = __floats2half2_rn(y0, y1);
            q[v4 * 2 + 1] = __floats2half2_rn(y2, y3);
        }
    }
}

// ---------------------------------------------------------------------------
// Kernel 2: fp16 HMMA GEMM, BK=64, 3-slot cp.async ring, 1 barrier/stage.
// C[M,N] = A[M,512](h,[M,K]) @ W(h,[K,N]) + bias (+R)
// CTA 128x128, 8 warps, warp tile 32x64. B fragments via ldmatrix.trans.
// ---------------------------------------------------------------------------
#define ASTR 72      // A slot row stride (64 + 8 pad)
#define BSTR 136     // B slot row stride (128 + 8 pad)
#define AHALVES (128 * ASTR)   // 9216
#define BHALVES (64 * BSTR)    // 8704
#define GSLOT (AHALVES + BHALVES)   // 17920 halves = 35840 B
#define GEMM_SMEM (3 * GSLOT * 2)   // 107520 bytes

template<bool HOUT>
__global__ __launch_bounds__(256) void gemm_hmma(
    const __half* __restrict__ A, const __half* __restrict__ W,
    const float* __restrict__ bias, const float* __restrict__ R,
    void* __restrict__ Cv, int N)
{
    extern __shared__ __half dsm[];

    int tid = threadIdx.x;
    int lane = tid & 31;
    int wid = tid >> 5;
    int wm = (wid & 3) * 32;
    int wn = (wid >> 2) * 64;
    int bm = blockIdx.y * 128;
    int bn = blockIdx.x * 128;

    float c[2][8][4];
    #pragma unroll
    for (int mi = 0; mi < 2; mi++)
        #pragma unroll
        for (int ni = 0; ni < 8; ni++)
            #pragma unroll
            for (int k = 0; k < 4; k++) c[mi][ni][k] = 0.f;

    // stage s (k-chunk of 64) into slot: A 128x64, B(W) 64x128
    auto stage = [&](int s, int slot) {
        __half* Ad = dsm + slot * GSLOT;
        __half* Bd = Ad + AHALVES;
        // A: 128 rows x 8 chunks(16B) = 1024 chunks, 4/thread
        #pragma unroll
        for (int i = 0; i < 4; i++) {
            int chunk = tid + i * 256;
            int r = chunk >> 3, c8 = (chunk & 7) * 8;
            CP_ASYNC16(smem_u32(&Ad[r * ASTR + c8]),
                       A + (size_t)(bm + r) * 512 + s * 64 + c8);
        }
        // B: 64 rows(k) x 16 chunks(n,16B) = 1024 chunks, 4/thread
        #pragma unroll
        for (int i = 0; i < 4; i++) {
            int chunk = tid + i * 256;
            int r = chunk >> 4, c8 = (chunk & 15) * 8;
            CP_ASYNC16(smem_u32(&Bd[r * BSTR + c8]),
                       W + (size_t)(s * 64 + r) * N + bn + c8);
        }
    };

    stage(0, 0); CP_COMMIT();
    stage(1, 1); CP_COMMIT();

    for (int s = 0; s < 8; s++) {
        if (s < 7) CP_WAIT(1);
        else       CP_WAIT(0);
        __syncthreads();   // all warps done with stage s-1 -> slot (s+2)%3 free
        if (s + 2 < 8) { stage(s + 2, (s + 2) % 3); CP_COMMIT(); }

        const __half* Ab = dsm + (s % 3) * GSLOT;
        const __half* Bb = Ab + AHALVES;
        #pragma unroll
        for (int kk = 0; kk < 4; kk++) {
            uint32_t a[2][4];
            #pragma unroll
            for (int mi = 0; mi < 2; mi++) {
                int row = wm + mi * 16 + (lane & 7) + ((lane >> 3) & 1) * 8;
                int kc = kk * 16 + ((lane >> 4) & 1) * 8;
                LDMATRIX_X4(a[mi][0], a[mi][1], a[mi][2], a[mi][3],
                            smem_u32(&Ab[row * ASTR + kc]));
            }
            uint32_t b[8][2];
            #pragma unroll
            for (int bi = 0; bi < 4; bi++) {
                // trans load from [K,N] tile: rows = k, cols = n
                int row = kk * 16 + ((lane >> 3) & 1) * 8 + (lane & 7);
                int col = wn + bi * 16 + (lane >> 4) * 8;
                uint32_t v0, v1, v2, v3;
                LDMATRIX_X4_T(v0, v1, v2, v3, smem_u32(&Bb[row * BSTR + col]));
                b[bi * 2 + 0][0] = v0; b[bi * 2 + 0][1] = v1;
                b[bi * 2 + 1][0] = v2; b[bi * 2 + 1][1] = v3;
            }
            #pragma unroll
            for (int mi = 0; mi < 2; mi++)
                #pragma unroll
                for (int ni = 0; ni < 8; ni++)
                    MMA16816(c[mi][ni], a[mi][0], a[mi][1], a[mi][2], a[mi][3],
                             b[ni][0], b[ni][1]);
        }
    }

    // epilogue
    #pragma unroll
    for (int mi = 0; mi < 2; mi++) {
        int r0 = bm + wm + mi * 16 + (lane >> 2);
        #pragma unroll
        for (int ni = 0; ni < 8; ni++) {
            int col = bn + wn + ni * 8 + (lane & 3) * 2;
            float bx = bias[col], by = bias[col + 1];
            float v00 = c[mi][ni][0] + bx, v01 = c[mi][ni][1] + by;
            float v10 = c[mi][ni][2] + bx, v11 = c[mi][ni][3] + by;
            if (HOUT) {
                __half* C = (__half*)Cv;
                *reinterpret_cast<__half2*>(C + (size_t)r0 * N + col) = __floats2half2_rn(v00, v01);
                *reinterpret_cast<__half2*>(C + (size_t)(r0 + 8) * N + col) = __floats2half2_rn(v10, v11);
            } else {
                float* C = (float*)Cv;
                if (R) {
                    const float2 ra = *reinterpret_cast<const float2*>(R + (size_t)r0 * N + col);
                    const float2 rb = *reinterpret_cast<const float2*>(R + (size_t)(r0 + 8) * N + col);
                    v00 += ra.x; v01 += ra.y; v10 += rb.x; v11 += rb.y;
                }
                *reinterpret_cast<float2*>(C + (size_t)r0 * N + col) = make_float2(v00, v01);
                *reinterpret_cast<float2*>(C + (size_t)(r0 + 8) * N + col) = make_float2(v10, v11);
            }
        }
    }
}

// ---------------------------------------------------------------------------
// Kernel 3: HMMA flash attention, 3-slot KV ring, 1 barrier/chunk (R8 form).
// ---------------------------------------------------------------------------
#define KSTR 72
#define QHALVES (128 * KSTR)        // 9216
#define KVSLOT  (2 * 64 * KSTR)     // K + V per slot = 9216 halves
#define ATTN_SMEM ((QHALVES + 3 * KVSLOT) * 2)    // 73728 bytes

__global__ __launch_bounds__(256) void attn_hmma(
    const __half* __restrict__ qkv, __half* __restrict__ out)
{
    extern __shared__ __half dsm[];
    __half* Qs = dsm;

    int b = blockIdx.z, h = blockIdx.y, qt = blockIdx.x;
    int tid = threadIdx.x, lane = tid & 31, wid = tid >> 5;

    const __half* base = qkv + (size_t)b * SEQ * C3 + h * HD;

    auto kslot = [&](int slot) -> __half* { return dsm + QHALVES + slot * KVSLOT; };

    auto stageKV = [&](int c, int slot) {
        __half* Kd = kslot(slot);
        __half* Vd = Kd + 64 * KSTR;
        #pragma unroll
        for (int i = 0; i < 2; i++) {
            int chunk = tid + i * 256;
            int r = chunk >> 3, c8 = (chunk & 7) * 8;
            const __half* kg = base + (size_t)(c * 64 + r) * C3 + CC + c8;
            CP_ASYNC16(smem_u32(&Kd[r * KSTR + c8]), kg);
            CP_ASYNC16(smem_u32(&Vd[r * KSTR + c8]), kg + CC);
        }
    };

    // prologue: Q + KV0 in group 0; KV1 in group 1
    #pragma unroll
    for (int i = 0; i < 4; i++) {
        int chunk = tid + i * 256;
        int r = chunk >> 3, c8 = (chunk & 7) * 8;
        CP_ASYNC16(smem_u32(&Qs[r * KSTR + c8]),
                   base + (size_t)(qt * 128 + r) * C3 + c8);
    }
    stageKV(0, 0); CP_COMMIT();
    stageKV(1, 1); CP_COMMIT();

    float o[8][4];
    #pragma unroll
    for (int i = 0; i < 8; i++)
        #pragma unroll
        for (int k = 0; k < 4; k++) o[i][k] = 0.f;
    float mrow0 = -1e30f, mrow1 = -1e30f, lrow0 = 0.f, lrow1 = 0.f;
    uint32_t qf[4][4];

    for (int ch = 0; ch < 16; ch++) {
        if (ch < 15) CP_WAIT(1);
        else         CP_WAIT(0);
        __syncthreads();   // frees slot (ch+2)%3 for staging
        if (ch + 2 < 16) { stageKV(ch + 2, (ch + 2) % 3); CP_COMMIT(); }

        const __half* Kb = kslot(ch % 3);
        const __half* Vb = Kb + 64 * KSTR;

        if (ch == 0) {
            #pragma unroll
            for (int ks = 0; ks < 4; ks++) {
                int row = wid * 16 + (lane & 7) + ((lane >> 3) & 1) * 8;
                int col = ks * 16 + ((lane >> 4) & 1) * 8;
                LDMATRIX_X4(qf[ks][0], qf[ks][1], qf[ks][2], qf[ks][3],
                            smem_u32(&Qs[row * KSTR + col]));
            }
        }

        // ---- S = Q @ K^T  (16 rows x 64 cols per warp) ----
        float sacc[8][4];
        #pragma unroll
        for (int j = 0; j < 8; j++)
            #pragma unroll
            for (int k = 0; k < 4; k++) sacc[j][k] = 0.f;

        #pragma unroll
        for (int j = 0; j < 8; j++) {
            uint32_t kf[8];
            uint32_t a0 = smem_u32(&Kb[(8 * j + (lane & 7)) * KSTR + (lane >> 3) * 8]);
            LDMATRIX_X4(kf[0], kf[1], kf[2], kf[3], a0);
            LDMATRIX_X4(kf[4], kf[5], kf[6], kf[7], a0 + 64);  // +32 halves
            #pragma unroll
            for (int ks = 0; ks < 4; ks++)
                MMA16816(sacc[j], qf[ks][0], qf[ks][1], qf[ks][2], qf[ks][3],
                         kf[2 * ks], kf[2 * ks + 1]);
        }

        // ---- online softmax (scale^2 = 1/64 folded here) ----
        const float sc = 1.0f / 64.0f;
        #pragma unroll
        for (int j = 0; j < 8; j++)
            #pragma unroll
            for (int k = 0; k < 4; k++) sacc[j][k] *= sc;

        float mx0 = mrow0, mx1 = mrow1;
        #pragma unroll
        for (int j = 0; j < 8; j++) {
            mx0 = fmaxf(mx0, fmaxf(sacc[j][0], sacc[j][1]));
            mx1 = fmaxf(mx1, fmaxf(sacc[j][2], sacc[j][3]));
        }
        mx0 = fmaxf(mx0, __shfl_xor_sync(0xFFFFFFFFu, mx0, 1));
        mx0 = fmaxf(mx0, __shfl_xor_sync(0xFFFFFFFFu, mx0, 2));
        mx1 = fmaxf(mx1, __shfl_xor_sync(0xFFFFFFFFu, mx1, 1));
        mx1 = fmaxf(mx1, __shfl_xor_sync(0xFFFFFFFFu, mx1, 2));

        float corr0 = __expf(mrow0 - mx0);
        float corr1 = __expf(mrow1 - mx1);
        mrow0 = mx0; mrow1 = mx1;
        lrow0 *= corr0; lrow1 *= corr1;
        #pragma unroll
        for (int nd = 0; nd < 8; nd++) {
            o[nd][0] *= corr0; o[nd][1] *= corr0;
            o[nd][2] *= corr1; o[nd][3] *= corr1;
        }

        uint32_t pf[4][4];
        #pragma unroll
        for (int jp = 0; jp < 4; jp++) {
            float p00 = __expf(sacc[2 * jp][0] - mx0);
            float p01 = __expf(sacc[2 * jp][1] - mx0);
            float p10 = __expf(sacc[2 * jp][2] - mx1);
            float p11 = __expf(sacc[2 * jp][3] - mx1);
            float p20 = __expf(sacc[2 * jp + 1][0] - mx0);
            float p21 = __expf(sacc[2 * jp + 1][1] - mx0);
            float p30 = __expf(sacc[2 * jp + 1][2] - mx1);
            float p31 = __expf(sacc[2 * jp + 1][3] - mx1);
            lrow0 += p00 + p01 + p20 + p21;
            lrow1 += p10 + p11 + p30 + p31;
            pf[jp][0] = f22u(p00, p01);
            pf[jp][1] = f22u(p10, p11);
            pf[jp][2] = f22u(p20, p21);
            pf[jp][3] = f22u(p30, p31);
        }

        // ---- O += P @ V ----
        #pragma unroll
        for (int ks = 0; ks < 4; ks++) {
            #pragma unroll
            for (int np = 0; np < 4; np++) {
                uint32_t v0, v1, v2, v3;
                int row = 16 * ks + ((lane >> 3) & 1) * 8 + (lane & 7);
                int col = np * 16 + (lane >> 4) * 8;
                LDMATRIX_X4_T(v0, v1, v2, v3, smem_u32(&Vb[row * KSTR + col]));
                MMA16816(o[2 * np], pf[ks][0], pf[ks][1], pf[ks][2], pf[ks][3], v0, v1);
                MMA16816(o[2 * np + 1], pf[ks][0], pf[ks][1], pf[ks][2], pf[ks][3], v2, v3);
            }
        }
    }

    // ---- finalize ----
    lrow0 += __shfl_xor_sync(0xFFFFFFFFu, lrow0, 1);
    lrow0 += __shfl_xor_sync(0xFFFFFFFFu, lrow0, 2);
    lrow1 += __shfl_xor_sync(0xFFFFFFFFu, lrow1, 1);
    lrow1 += __shfl_xor_sync(0xFFFFFFFFu, lrow1, 2);
    float inv0 = 1.0f / lrow0, inv1 = 1.0f / lrow1;

    int r0 = qt * 128 + wid * 16 + (lane >> 2);
    __half* ob = out + (size_t)b * SEQ * CC + h * HD;
    #pragma unroll
    for (int nd = 0; nd < 8; nd++) {
        int col = nd * 8 + (lane & 3) * 2;
        *reinterpret_cast<__half2*>(ob + (size_t)r0 * CC + col) =
            __floats2half2_rn(o[nd][0] * inv0, o[nd][1] * inv0);
        *reinterpret_cast<__half2*>(ob + (size_t)(r0 + 8) * CC + col) =
            __floats2half2_rn(o[nd][2] * inv1, o[nd][3] * inv1);
    }
}

// ---------------------------------------------------------------------------
// Launch
// ---------------------------------------------------------------------------
extern "C" void kernel_launch(void* const* d_in, const int* in_sizes, int n_in,
                              void* d_out, int out_size)
{
    const float* x        = (const float*)d_in[0];
    const float* gn_scale = (const float*)d_in[1];
    const float* gn_bias  = (const float*)d_in[2];
    const float* w_qkv    = (const float*)d_in[3];
    const float* b_qkv    = (const float*)d_in[4];
    const float* w_out    = (const float*)d_in[5];
    const float* b_out    = (const float*)d_in[6];
    float* out            = (float*)d_out;

    __half* xn;   cudaGetSymbolAddress((void**)&xn,   g_xn_h);
    __half* qkv;  cudaGetSymbolAddress((void**)&qkv,  g_qkv_h);
    __half* attn; cudaGetSymbolAddress((void**)&attn, g_attn_h);
    __half* whq;  cudaGetSymbolAddress((void**)&whq,  g_wh_qkv);
    __half* who;  cudaGetSymbolAddress((void**)&who,  g_wh_out);

    cudaFuncSetAttribute(gemm_hmma<true>,  cudaFuncAttributeMaxDynamicSharedMemorySize, GEMM_SMEM);
    cudaFuncSetAttribute(gemm_hmma<false>, cudaFuncAttributeMaxDynamicSharedMemorySize, GEMM_SMEM);
    cudaFuncSetAttribute(attn_hmma,        cudaFuncAttributeMaxDynamicSharedMemorySize, ATTN_SMEM);

    // 0) weight converts (fp32 -> fp16, layout preserved)
    wconv_kernel<<<(CC * C3 / 4 + 255) / 256, 256>>>(w_qkv, whq, CC * C3);
    wconv_kernel<<<(CC * CC / 4 + 255) / 256, 256>>>(w_out, who, CC * CC);

    // 1) GroupNorm -> fp16
    gn_kernel<<<BB * NG, 256>>>(x, gn_scale, gn_bias, xn);

    // 2) QKV projection (HMMA, fp16 out)
    gemm_hmma<true><<<dim3(C3 / 128, (BB * SEQ) / 128), 256, GEMM_SMEM>>>(xn, whq, b_qkv, nullptr, qkv, C3);

    // 3) Attention (HMMA flash)
    attn_hmma<<<dim3(SEQ / 128, NH, BB), 256, ATTN_SMEM>>>(qkv, attn);

    // 4) Output projection + bias + residual (HMMA, fp32 out)
    gemm_hmma<false><<<dim3(CC / 128, (BB * SEQ) / 128), 256, GEMM_SMEM>>>(attn, who, b_out, x, out, CC);
}

// round 12
// speedup vs baseline: 1.1663x; 1.1459x over previous
#include <cuda_runtime.h>
#include <cuda_fp16.h>
#include <cstdint>

// Problem constants
#define BB 8
#define SEQ 1024
#define CC 512
#define NH 8
#define HD 64
#define NG 32
#define GSZ 16
#define C3 1536

// Scratch
__device__ __half g_xn_h[BB * SEQ * CC];    // normalized x (fp16)
__device__ __half g_qkv_h[BB * SEQ * C3];   // qkv projection (fp16)
__device__ __half g_attn_h[BB * SEQ * CC];  // attention output (fp16)
__device__ __half g_wh_qkv[CC * C3];        // w_qkv [K,N] fp16
__device__ __half g_wh_out[CC * CC];        // w_out [K,N] fp16

// ---------------------------------------------------------------------------
// helpers
// ---------------------------------------------------------------------------
__device__ __forceinline__ uint32_t smem_u32(const void* p) {
    uint32_t a; asm("{ .reg .u64 t; cvta.to.shared.u64 t, %1; cvt.u32.u64 %0, t; }" : "=r"(a) : "l"(p));
    return a;
}
__device__ __forceinline__ uint32_t f22u(float a, float b) {
    __half2 h = __floats2half2_rn(a, b);
    return *reinterpret_cast<uint32_t*>(&h);
}

#define CP_ASYNC16(sa, ga) \
    asm volatile("cp.async.cg.shared.global [%0], [%1], 16;" :: "r"(sa), "l"(ga))
#define CP_COMMIT() asm volatile("cp.async.commit_group;")
#define CP_WAIT(n)  asm volatile("cp.async.wait_group %0;" :: "n"(n))

#define LDMATRIX_X4(r0, r1, r2, r3, addr) \
    asm volatile("ldmatrix.sync.aligned.m8n8.x4.shared.b16 {%0,%1,%2,%3}, [%4];" \
        : "=r"(r0), "=r"(r1), "=r"(r2), "=r"(r3) : "r"(addr))

#define LDMATRIX_X4_T(r0, r1, r2, r3, addr) \
    asm volatile("ldmatrix.sync.aligned.m8n8.x4.trans.shared.b16 {%0,%1,%2,%3}, [%4];" \
        : "=r"(r0), "=r"(r1), "=r"(r2), "=r"(r3) : "r"(addr))

#define MMA16816(c, a0, a1, a2, a3, b0, b1) \
    asm volatile("mma.sync.aligned.m16n8k16.row.col.f32.f16.f16.f32 " \
        "{%0,%1,%2,%3}, {%4,%5,%6,%7}, {%8,%9}, {%0,%1,%2,%3};" \
        : "+f"((c)[0]), "+f"((c)[1]), "+f"((c)[2]), "+f"((c)[3]) \
        : "r"(a0), "r"(a1), "r"(a2), "r"(a3), "r"(b0), "r"(b1))

// ---------------------------------------------------------------------------
// Kernel 0: weight convert f32 -> f16 (same [K,N] layout, no transpose)
// ---------------------------------------------------------------------------
__global__ __launch_bounds__(256) void wconv_kernel(
    const float* __restrict__ W, __half* __restrict__ Wh, int n)
{
    int i = (blockIdx.x * 256 + threadIdx.x) * 4;
    if (i < n) {
        float4 v = *reinterpret_cast<const float4*>(W + i);
        __half2* o = reinterpret_cast<__half2*>(Wh + i);
        o[0] = __floats2half2_rn(v.x, v.y);
        o[1] = __floats2half2_rn(v.z, v.w);
    }
}

// ---------------------------------------------------------------------------
// Kernel 1: GroupNorm -> fp16. Quad-coalesced: 4 consecutive threads cover one
// row's 16 channels (64B contiguous), warp covers 8 rows.
// ---------------------------------------------------------------------------
__global__ __launch_bounds__(256) void gn_kernel(
    const float* __restrict__ x, const float* __restrict__ gamma,
    const float* __restrict__ beta, __half* __restrict__ xn)
{
    int bg = blockIdx.x;
    int b = bg >> 5, g = bg & 31;
    const float* base = x + (size_t)b * SEQ * CC + g * GSZ;
    int tid = threadIdx.x;
    int q4 = tid & 3;        // float4 index within the 16-channel group
    int sbase = tid >> 2;    // 0..63

    float sum = 0.f, sq = 0.f;
    #pragma unroll
    for (int i = 0; i < 16; i++) {
        int s = sbase + i * 64;
        float4 v = *reinterpret_cast<const float4*>(base + (size_t)s * CC + q4 * 4);
        sum += v.x + v.y + v.z + v.w;
        sq  += v.x * v.x + v.y * v.y + v.z * v.z + v.w * v.w;
    }
    #pragma unroll
    for (int off = 16; off; off >>= 1) {
        sum += __shfl_xor_sync(0xFFFFFFFFu, sum, off);
        sq  += __shfl_xor_sync(0xFFFFFFFFu, sq, off);
    }
    __shared__ float red[2][8];
    __shared__ float stats[2];
    int wid = tid >> 5, lid = tid & 31;
    if (lid == 0) { red[0][wid] = sum; red[1][wid] = sq; }
    __syncthreads();
    if (tid == 0) {
        float S = 0.f, Q = 0.f;
        #pragma unroll
        for (int w = 0; w < 8; w++) { S += red[0][w]; Q += red[1][w]; }
        float mu = S * (1.f / 16384.f);
        float var = Q * (1.f / 16384.f) - mu * mu;
        stats[0] = mu;
        stats[1] = rsqrtf(var + 1e-6f);
    }
    __syncthreads();
    float mu = stats[0], rstd = stats[1];

    float ga[4], be[4];
    #pragma unroll
    for (int c = 0; c < 4; c++) {
        ga[c] = gamma[g * GSZ + q4 * 4 + c] * rstd;
        be[c] = beta[g * GSZ + q4 * 4 + c];
    }
    __half* obase = xn + (size_t)b * SEQ * CC + g * GSZ;
    #pragma unroll
    for (int i = 0; i < 16; i++) {
        int s = sbase + i * 64;
        float4 v = *reinterpret_cast<const float4*>(base + (size_t)s * CC + q4 * 4);
        float y0 = (v.x - mu) * ga[0] + be[0];
        float y1 = (v.y - mu) * ga[1] + be[1];
        float y2 = (v.z - mu) * ga[2] + be[2];
        float y3 = (v.w - mu) * ga[3] + be[3];
        __half2* q = reinterpret_cast<__half2*>(obase + (size_t)s * CC + q4 * 4);
        q[0] = __floats2half2_rn(y0, y1);
        q[1] = __floats2half2_rn(y2, y3);
    }
}

// ---------------------------------------------------------------------------
// Kernel 2: fp16 HMMA GEMM, BK=32, 4-slot cp.async ring (R8 cadence),
// B consumed in [K,N] layout via ldmatrix.trans (R10-verified mapping).
// CTA 128x128, 8 warps, warp tile 32x64. regs capped for 2 CTAs/SM.
// ---------------------------------------------------------------------------
#define ASTR 40      // A slot row stride (32 + 8 pad), halves
#define BSTR 136     // B slot row stride (128 + 8 pad), halves
#define AHALVES (128 * ASTR)        // 5120
#define BHALVES (32 * BSTR)         // 4352
#define GSLOT (AHALVES + BHALVES)   // 9472 halves
#define GEMM_SMEM (4 * GSLOT * 2)   // 75776 bytes

template<bool HOUT>
__global__ __launch_bounds__(256, 2) void gemm_hmma(
    const __half* __restrict__ A, const __half* __restrict__ W,
    const float* __restrict__ bias, const float* __restrict__ R,
    void* __restrict__ Cv, int N)
{
    extern __shared__ __half dsm[];

    int tid = threadIdx.x;
    int lane = tid & 31;
    int wid = tid >> 5;
    int wm = (wid & 3) * 32;
    int wn = (wid >> 2) * 64;
    int bm = blockIdx.y * 128;
    int bn = blockIdx.x * 128;

    float c[2][8][4];
    #pragma unroll
    for (int mi = 0; mi < 2; mi++)
        #pragma unroll
        for (int ni = 0; ni < 8; ni++)
            #pragma unroll
            for (int k = 0; k < 4; k++) c[mi][ni][k] = 0.f;

    // stage s (k-chunk of 32): A 128x32, B(W) 32x128
    auto stage = [&](int s, int slot) {
        __half* Ad = dsm + slot * GSLOT;
        __half* Bd = Ad + AHALVES;
        // A: 128 rows x 4 chunks(16B) = 512 chunks, 2/thread
        #pragma unroll
        for (int i = 0; i < 2; i++) {
            int chunk = tid + i * 256;
            int r = chunk >> 2, c8 = (chunk & 3) * 8;
            CP_ASYNC16(smem_u32(&Ad[r * ASTR + c8]),
                       A + (size_t)(bm + r) * 512 + s * 32 + c8);
        }
        // B: 32 rows(k) x 16 chunks(n,16B) = 512 chunks, 2/thread
        #pragma unroll
        for (int i = 0; i < 2; i++) {
            int chunk = tid + i * 256;
            int r = chunk >> 4, c8 = (chunk & 15) * 8;
            CP_ASYNC16(smem_u32(&Bd[r * BSTR + c8]),
                       W + (size_t)(s * 32 + r) * N + bn + c8);
        }
    };

    stage(0, 0); CP_COMMIT();
    stage(1, 1); CP_COMMIT();
    stage(2, 2); CP_COMMIT();

    for (int s = 0; s < 16; s++) {
        int rem = 15 - s;
        if (rem >= 2)      CP_WAIT(2);
        else if (rem == 1) CP_WAIT(1);
        else               CP_WAIT(0);
        __syncthreads();   // all warps done with stage s-1 -> slot (s+3)&3 free
        if (s + 3 < 16) { stage(s + 3, (s + 3) & 3); CP_COMMIT(); }

        const __half* Ab = dsm + (s & 3) * GSLOT;
        const __half* Bb = Ab + AHALVES;
        #pragma unroll
        for (int kk = 0; kk < 2; kk++) {
            uint32_t a[2][4];
            #pragma unroll
            for (int mi = 0; mi < 2; mi++) {
                int row = wm + mi * 16 + (lane & 7) + ((lane >> 3) & 1) * 8;
                int kc = kk * 16 + ((lane >> 4) & 1) * 8;
                LDMATRIX_X4(a[mi][0], a[mi][1], a[mi][2], a[mi][3],
                            smem_u32(&Ab[row * ASTR + kc]));
            }
            uint32_t b[8][2];
            #pragma unroll
            for (int bi = 0; bi < 4; bi++) {
                // trans load from [K,N] tile: rows = k, cols = n
                int row = kk * 16 + ((lane >> 3) & 1) * 8 + (lane & 7);
                int col = wn + bi * 16 + (lane >> 4) * 8;
                uint32_t v0, v1, v2, v3;
                LDMATRIX_X4_T(v0, v1, v2, v3, smem_u32(&Bb[row * BSTR + col]));
                b[bi * 2 + 0][0] = v0; b[bi * 2 + 0][1] = v1;
                b[bi * 2 + 1][0] = v2; b[bi * 2 + 1][1] = v3;
            }
            #pragma unroll
            for (int mi = 0; mi < 2; mi++)
                #pragma unroll
                for (int ni = 0; ni < 8; ni++)
                    MMA16816(c[mi][ni], a[mi][0], a[mi][1], a[mi][2], a[mi][3],
                             b[ni][0], b[ni][1]);
        }
    }

    // epilogue
    #pragma unroll
    for (int mi = 0; mi < 2; mi++) {
        int r0 = bm + wm + mi * 16 + (lane >> 2);
        #pragma unroll
        for (int ni = 0; ni < 8; ni++) {
            int col = bn + wn + ni * 8 + (lane & 3) * 2;
            float bx = bias[col], by = bias[col + 1];
            float v00 = c[mi][ni][0] + bx, v01 = c[mi][ni][1] + by;
            float v10 = c[mi][ni][2] + bx, v11 = c[mi][ni][3] + by;
            if (HOUT) {
                __half* C = (__half*)Cv;
                *reinterpret_cast<__half2*>(C + (size_t)r0 * N + col) = __floats2half2_rn(v00, v01);
                *reinterpret_cast<__half2*>(C + (size_t)(r0 + 8) * N + col) = __floats2half2_rn(v10, v11);
            } else {
                float* C = (float*)Cv;
                if (R) {
                    const float2 ra = *reinterpret_cast<const float2*>(R + (size_t)r0 * N + col);
                    const float2 rb = *reinterpret_cast<const float2*>(R + (size_t)(r0 + 8) * N + col);
                    v00 += ra.x; v01 += ra.y; v10 += rb.x; v11 += rb.y;
                }
                *reinterpret_cast<float2*>(C + (size_t)r0 * N + col) = make_float2(v00, v01);
                *reinterpret_cast<float2*>(C + (size_t)(r0 + 8) * N + col) = make_float2(v10, v11);
            }
        }
    }
}

// ---------------------------------------------------------------------------
// Kernel 3: HMMA flash attention, 3-slot KV ring, 1 barrier/chunk.
// regs capped (256,2) for 2 CTAs/SM residency.
// ---------------------------------------------------------------------------
#define KSTR 72
#define QHALVES (128 * KSTR)        // 9216
#define KVSLOT  (2 * 64 * KSTR)     // K + V per slot = 9216 halves
#define ATTN_SMEM ((QHALVES + 3 * KVSLOT) * 2)    // 73728 bytes

__global__ __launch_bounds__(256, 2) void attn_hmma(
    const __half* __restrict__ qkv, __half* __restrict__ out)
{
    extern __shared__ __half dsm[];
    __half* Qs = dsm;

    int b = blockIdx.z, h = blockIdx.y, qt = blockIdx.x;
    int tid = threadIdx.x, lane = tid & 31, wid = tid >> 5;

    const __half* base = qkv + (size_t)b * SEQ * C3 + h * HD;

    auto kslot = [&](int slot) -> __half* { return dsm + QHALVES + slot * KVSLOT; };

    auto stageKV = [&](int c, int slot) {
        __half* Kd = kslot(slot);
        __half* Vd = Kd + 64 * KSTR;
        #pragma unroll
        for (int i = 0; i < 2; i++) {
            int chunk = tid + i * 256;
            int r = chunk >> 3, c8 = (chunk & 7) * 8;
            const __half* kg = base + (size_t)(c * 64 + r) * C3 + CC + c8;
            CP_ASYNC16(smem_u32(&Kd[r * KSTR + c8]), kg);
            CP_ASYNC16(smem_u32(&Vd[r * KSTR + c8]), kg + CC);
        }
    };

    // prologue: Q + KV0 in group 0; KV1 in group 1
    #pragma unroll
    for (int i = 0; i < 4; i++) {
        int chunk = tid + i * 256;
        int r = chunk >> 3, c8 = (chunk & 7) * 8;
        CP_ASYNC16(smem_u32(&Qs[r * KSTR + c8]),
                   base + (size_t)(qt * 128 + r) * C3 + c8);
    }
    stageKV(0, 0); CP_COMMIT();
    stageKV(1, 1); CP_COMMIT();

    float o[8][4];
    #pragma unroll
    for (int i = 0; i < 8; i++)
        #pragma unroll
        for (int k = 0; k < 4; k++) o[i][k] = 0.f;
    float mrow0 = -1e30f, mrow1 = -1e30f, lrow0 = 0.f, lrow1 = 0.f;
    uint32_t qf[4][4];

    for (int ch = 0; ch < 16; ch++) {
        if (ch < 15) CP_WAIT(1);
        else         CP_WAIT(0);
        __syncthreads();   // frees slot (ch+2)%3 for staging
        if (ch + 2 < 16) { stageKV(ch + 2, (ch + 2) % 3); CP_COMMIT(); }

        const __half* Kb = kslot(ch % 3);
        const __half* Vb = Kb + 64 * KSTR;

        if (ch == 0) {
            #pragma unroll
            for (int ks = 0; ks < 4; ks++) {
                int row = wid * 16 + (lane & 7) + ((lane >> 3) & 1) * 8;
                int col = ks * 16 + ((lane >> 4) & 1) * 8;
                LDMATRIX_X4(qf[ks][0], qf[ks][1], qf[ks][2], qf[ks][3],
                            smem_u32(&Qs[row * KSTR + col]));
            }
        }

        // ---- S = Q @ K^T  (16 rows x 64 cols per warp) ----
        float sacc[8][4];
        #pragma unroll
        for (int j = 0; j < 8; j++)
            #pragma unroll
            for (int k = 0; k < 4; k++) sacc[j][k] = 0.f;

        #pragma unroll
        for (int j = 0; j < 8; j++) {
            uint32_t kf[8];
            uint32_t a0 = smem_u32(&Kb[(8 * j + (lane & 7)) * KSTR + (lane >> 3) * 8]);
            LDMATRIX_X4(kf[0], kf[1], kf[2], kf[3], a0);
            LDMATRIX_X4(kf[4], kf[5], kf[6], kf[7], a0 + 64);  // +32 halves
            #pragma unroll
            for (int ks = 0; ks < 4; ks++)
                MMA16816(sacc[j], qf[ks][0], qf[ks][1], qf[ks][2], qf[ks][3],
                         kf[2 * ks], kf[2 * ks + 1]);
        }

        // ---- online softmax (scale^2 = 1/64 folded here) ----
        const float sc = 1.0f / 64.0f;
        #pragma unroll
        for (int j = 0; j < 8; j++)
            #pragma unroll
            for (int k = 0; k < 4; k++) sacc[j][k] *= sc;

        float mx0 = mrow0, mx1 = mrow1;
        #pragma unroll
        for (int j = 0; j < 8; j++) {
            mx0 = fmaxf(mx0, fmaxf(sacc[j][0], sacc[j][1]));
            mx1 = fmaxf(mx1, fmaxf(sacc[j][2], sacc[j][3]));
        }
        mx0 = fmaxf(mx0, __shfl_xor_sync(0xFFFFFFFFu, mx0, 1));
        mx0 = fmaxf(mx0, __shfl_xor_sync(0xFFFFFFFFu, mx0, 2));
        mx1 = fmaxf(mx1, __shfl_xor_sync(0xFFFFFFFFu, mx1, 1));
        mx1 = fmaxf(mx1, __shfl_xor_sync(0xFFFFFFFFu, mx1, 2));

        float corr0 = __expf(mrow0 - mx0);
        float corr1 = __expf(mrow1 - mx1);
        mrow0 = mx0; mrow1 = mx1;
        lrow0 *= corr0; lrow1 *= corr1;
        #pragma unroll
        for (int nd = 0; nd < 8; nd++) {
            o[nd][0] *= corr0; o[nd][1] *= corr0;
            o[nd][2] *= corr1; o[nd][3] *= corr1;
        }

        uint32_t pf[4][4];
        #pragma unroll
        for (int jp = 0; jp < 4; jp++) {
            float p00 = __expf(sacc[2 * jp][0] - mx0);
            float p01 = __expf(sacc[2 * jp][1] - mx0);
            float p10 = __expf(sacc[2 * jp][2] - mx1);
            float p11 = __expf(sacc[2 * jp][3] - mx1);
            float p20 = __expf(sacc[2 * jp + 1][0] - mx0);
            float p21 = __expf(sacc[2 * jp + 1][1] - mx0);
            float p30 = __expf(sacc[2 * jp + 1][2] - mx1);
            float p31 = __expf(sacc[2 * jp + 1][3] - mx1);
            lrow0 += p00 + p01 + p20 + p21;
            lrow1 += p10 + p11 + p30 + p31;
            pf[jp][0] = f22u(p00, p01);
            pf[jp][1] = f22u(p10, p11);
            pf[jp][2] = f22u(p20, p21);
            pf[jp][3] = f22u(p30, p31);
        }

        // ---- O += P @ V ----
        #pragma unroll
        for (int ks = 0; ks < 4; ks++) {
            #pragma unroll
            for (int np = 0; np < 4; np++) {
                uint32_t v0, v1, v2, v3;
                int row = 16 * ks + ((lane >> 3) & 1) * 8 + (lane & 7);
                int col = np * 16 + (lane >> 4) * 8;
                LDMATRIX_X4_T(v0, v1, v2, v3, smem_u32(&Vb[row * KSTR + col]));
                MMA16816(o[2 * np], pf[ks][0], pf[ks][1], pf[ks][2], pf[ks][3], v0, v1);
                MMA16816(o[2 * np + 1], pf[ks][0], pf[ks][1], pf[ks][2], pf[ks][3], v2, v3);
            }
        }
    }

    // ---- finalize ----
    lrow0 += __shfl_xor_sync(0xFFFFFFFFu, lrow0, 1);
    lrow0 += __shfl_xor_sync(0xFFFFFFFFu, lrow0, 2);
    lrow1 += __shfl_xor_sync(0xFFFFFFFFu, lrow1, 1);
    lrow1 += __shfl_xor_sync(0xFFFFFFFFu, lrow1, 2);
    float inv0 = 1.0f / lrow0, inv1 = 1.0f / lrow1;

    int r0 = qt * 128 + wid * 16 + (lane >> 2);
    __half* ob = out + (size_t)b * SEQ * CC + h * HD;
    #pragma unroll
    for (int nd = 0; nd < 8; nd++) {
        int col = nd * 8 + (lane & 3) * 2;
        *reinterpret_cast<__half2*>(ob + (size_t)r0 * CC + col) =
            __floats2half2_rn(o[nd][0] * inv0, o[nd][1] * inv0);
        *reinterpret_cast<__half2*>(ob + (size_t)(r0 + 8) * CC + col) =
            __floats2half2_rn(o[nd][2] * inv1, o[nd][3] * inv1);
    }
}

// ---------------------------------------------------------------------------
// Launch
// ---------------------------------------------------------------------------
extern "C" void kernel_launch(void* const* d_in, const int* in_sizes, int n_in,
                              void* d_out, int out_size)
{
    const float* x        = (const float*)d_in[0];
    const float* gn_scale = (const float*)d_in[1];
    const float* gn_bias  = (const float*)d_in[2];
    const float* w_qkv    = (const float*)d_in[3];
    const float* b_qkv    = (const float*)d_in[4];
    const float* w_out    = (const float*)d_in[5];
    const float* b_out    = (const float*)d_in[6];
    float* out            = (float*)d_out;

    __half* xn;   cudaGetSymbolAddress((void**)&xn,   g_xn_h);
    __half* qkv;  cudaGetSymbolAddress((void**)&qkv,  g_qkv_h);
    __half* attn; cudaGetSymbolAddress((void**)&attn, g_attn_h);
    __half* whq;  cudaGetSymbolAddress((void**)&whq,  g_wh_qkv);
    __half* who;  cudaGetSymbolAddress((void**)&who,  g_wh_out);

    cudaFuncSetAttribute(gemm_hmma<true>,  cudaFuncAttributeMaxDynamicSharedMemorySize, GEMM_SMEM);
    cudaFuncSetAttribute(gemm_hmma<false>, cudaFuncAttributeMaxDynamicSharedMemorySize, GEMM_SMEM);
    cudaFuncSetAttribute(attn_hmma,        cudaFuncAttributeMaxDynamicSharedMemorySize, ATTN_SMEM);

    // 0) weight converts (fp32 -> fp16, layout preserved)
    wconv_kernel<<<(CC * C3 / 4 + 255) / 256, 256>>>(w_qkv, whq, CC * C3);
    wconv_kernel<<<(CC * CC / 4 + 255) / 256, 256>>>(w_out, who, CC * CC);

    // 1) GroupNorm -> fp16
    gn_kernel<<<BB * NG, 256>>>(x, gn_scale, gn_bias, xn);

    // 2) QKV projection (HMMA, fp16 out)
    gemm_hmma<true><<<dim3(C3 / 128, (BB * SEQ) / 128), 256, GEMM_SMEM>>>(xn, whq, b_qkv, nullptr, qkv, C3);

    // 3) Attention (HMMA flash)
    attn_hmma<<<dim3(SEQ / 128, NH, BB), 256, ATTN_SMEM>>>(qkv, attn);

    // 4) Output projection + bias + residual (HMMA, fp32 out)
    gemm_hmma<false><<<dim3(CC / 128, (BB * SEQ) / 128), 256, GEMM_SMEM>>>(attn, who, b_out, x, out, CC);
}

// round 13
// speedup vs baseline: 1.1930x; 1.0229x over previous
#include <cuda_runtime.h>
#include <cuda_fp16.h>
#include <cstdint>

// Problem constants
#define BB 8
#define SEQ 1024
#define CC 512
#define NH 8
#define HD 64
#define NG 32
#define GSZ 16
#define C3 1536

// Scratch
__device__ __half g_xn_h[BB * SEQ * CC];    // normalized x (fp16)
__device__ __half g_qkv_h[BB * SEQ * C3];   // qkv projection (fp16)
__device__ __half g_attn_h[BB * SEQ * CC];  // attention output (fp16)
__device__ __half g_wh_qkv[CC * C3];        // w_qkv [K,N] fp16
__device__ __half g_wh_out[CC * CC];        // w_out [K,N] fp16

// ---------------------------------------------------------------------------
// helpers
// ---------------------------------------------------------------------------
__device__ __forceinline__ uint32_t smem_u32(const void* p) {
    uint32_t a; asm("{ .reg .u64 t; cvta.to.shared.u64 t, %1; cvt.u32.u64 %0, t; }" : "=r"(a) : "l"(p));
    return a;
}
// packed fp16 exp2 of (a, b): one MUFU op for two values
__device__ __forceinline__ uint32_t ex2h2(float a, float b) {
    __half2 h = __floats2half2_rn(a, b);
    uint32_t u = *reinterpret_cast<uint32_t*>(&h);
    uint32_t r; asm("ex2.approx.f16x2 %0, %1;" : "=r"(r) : "r"(u));
    return r;
}

#define CP_ASYNC16(sa, ga) \
    asm volatile("cp.async.cg.shared.global [%0], [%1], 16;" :: "r"(sa), "l"(ga))
#define CP_COMMIT() asm volatile("cp.async.commit_group;")
#define CP_WAIT(n)  asm volatile("cp.async.wait_group %0;" :: "n"(n))

#define LDMATRIX_X4(r0, r1, r2, r3, addr) \
    asm volatile("ldmatrix.sync.aligned.m8n8.x4.shared.b16 {%0,%1,%2,%3}, [%4];" \
        : "=r"(r0), "=r"(r1), "=r"(r2), "=r"(r3) : "r"(addr))

#define LDMATRIX_X4_T(r0, r1, r2, r3, addr) \
    asm volatile("ldmatrix.sync.aligned.m8n8.x4.trans.shared.b16 {%0,%1,%2,%3}, [%4];" \
        : "=r"(r0), "=r"(r1), "=r"(r2), "=r"(r3) : "r"(addr))

#define MMA16816(c, a0, a1, a2, a3, b0, b1) \
    asm volatile("mma.sync.aligned.m16n8k16.row.col.f32.f16.f16.f32 " \
        "{%0,%1,%2,%3}, {%4,%5,%6,%7}, {%8,%9}, {%0,%1,%2,%3};" \
        : "+f"((c)[0]), "+f"((c)[1]), "+f"((c)[2]), "+f"((c)[3]) \
        : "r"(a0), "r"(a1), "r"(a2), "r"(a3), "r"(b0), "r"(b1))

// ---------------------------------------------------------------------------
// Kernel 0: weight convert f32 -> f16 (same [K,N] layout, no transpose)
// ---------------------------------------------------------------------------
__global__ __launch_bounds__(256) void wconv_kernel(
    const float* __restrict__ W, __half* __restrict__ Wh, int n)
{
    int i = (blockIdx.x * 256 + threadIdx.x) * 4;
    if (i < n) {
        float4 v = *reinterpret_cast<const float4*>(W + i);
        __half2* o = reinterpret_cast<__half2*>(Wh + i);
        o[0] = __floats2half2_rn(v.x, v.y);
        o[1] = __floats2half2_rn(v.z, v.w);
    }
}

// ---------------------------------------------------------------------------
// Kernel 1: GroupNorm -> fp16. Quad-coalesced.
// ---------------------------------------------------------------------------
__global__ __launch_bounds__(256) void gn_kernel(
    const float* __restrict__ x, const float* __restrict__ gamma,
    const float* __restrict__ beta, __half* __restrict__ xn)
{
    int bg = blockIdx.x;
    int b = bg >> 5, g = bg & 31;
    const float* base = x + (size_t)b * SEQ * CC + g * GSZ;
    int tid = threadIdx.x;
    int q4 = tid & 3;
    int sbase = tid >> 2;

    float sum = 0.f, sq = 0.f;
    #pragma unroll
    for (int i = 0; i < 16; i++) {
        int s = sbase + i * 64;
        float4 v = *reinterpret_cast<const float4*>(base + (size_t)s * CC + q4 * 4);
        sum += v.x + v.y + v.z + v.w;
        sq  += v.x * v.x + v.y * v.y + v.z * v.z + v.w * v.w;
    }
    #pragma unroll
    for (int off = 16; off; off >>= 1) {
        sum += __shfl_xor_sync(0xFFFFFFFFu, sum, off);
        sq  += __shfl_xor_sync(0xFFFFFFFFu, sq, off);
    }
    __shared__ float red[2][8];
    __shared__ float stats[2];
    int wid = tid >> 5, lid = tid & 31;
    if (lid == 0) { red[0][wid] = sum; red[1][wid] = sq; }
    __syncthreads();
    if (tid == 0) {
        float S = 0.f, Q = 0.f;
        #pragma unroll
        for (int w = 0; w < 8; w++) { S += red[0][w]; Q += red[1][w]; }
        float mu = S * (1.f / 16384.f);
        float var = Q * (1.f / 16384.f) - mu * mu;
        stats[0] = mu;
        stats[1] = rsqrtf(var + 1e-6f);
    }
    __syncthreads();
    float mu = stats[0], rstd = stats[1];

    float ga[4], be[4];
    #pragma unroll
    for (int c = 0; c < 4; c++) {
        ga[c] = gamma[g * GSZ + q4 * 4 + c] * rstd;
        be[c] = beta[g * GSZ + q4 * 4 + c];
    }
    __half* obase = xn + (size_t)b * SEQ * CC + g * GSZ;
    #pragma unroll
    for (int i = 0; i < 16; i++) {
        int s = sbase + i * 64;
        float4 v = *reinterpret_cast<const float4*>(base + (size_t)s * CC + q4 * 4);
        float y0 = (v.x - mu) * ga[0] + be[0];
        float y1 = (v.y - mu) * ga[1] + be[1];
        float y2 = (v.z - mu) * ga[2] + be[2];
        float y3 = (v.w - mu) * ga[3] + be[3];
        __half2* q = reinterpret_cast<__half2*>(obase + (size_t)s * CC + q4 * 4);
        q[0] = __floats2half2_rn(y0, y1);
        q[1] = __floats2half2_rn(y2, y3);
    }
}

// ---------------------------------------------------------------------------
// Kernel 2: fp16 HMMA GEMM, BK=32, 4-slot cp.async ring (unchanged R12 WIN).
// ---------------------------------------------------------------------------
#define ASTR 40
#define BSTR 136
#define AHALVES (128 * ASTR)
#define BHALVES (32 * BSTR)
#define GSLOT (AHALVES + BHALVES)
#define GEMM_SMEM (4 * GSLOT * 2)

template<bool HOUT>
__global__ __launch_bounds__(256, 2) void gemm_hmma(
    const __half* __restrict__ A, const __half* __restrict__ W,
    const float* __restrict__ bias, const float* __restrict__ R,
    void* __restrict__ Cv, int N)
{
    extern __shared__ __half dsm[];

    int tid = threadIdx.x;
    int lane = tid & 31;
    int wid = tid >> 5;
    int wm = (wid & 3) * 32;
    int wn = (wid >> 2) * 64;
    int bm = blockIdx.y * 128;
    int bn = blockIdx.x * 128;

    float c[2][8][4];
    #pragma unroll
    for (int mi = 0; mi < 2; mi++)
        #pragma unroll
        for (int ni = 0; ni < 8; ni++)
            #pragma unroll
            for (int k = 0; k < 4; k++) c[mi][ni][k] = 0.f;

    auto stage = [&](int s, int slot) {
        __half* Ad = dsm + slot * GSLOT;
        __half* Bd = Ad + AHALVES;
        #pragma unroll
        for (int i = 0; i < 2; i++) {
            int chunk = tid + i * 256;
            int r = chunk >> 2, c8 = (chunk & 3) * 8;
            CP_ASYNC16(smem_u32(&Ad[r * ASTR + c8]),
                       A + (size_t)(bm + r) * 512 + s * 32 + c8);
        }
        #pragma unroll
        for (int i = 0; i < 2; i++) {
            int chunk = tid + i * 256;
            int r = chunk >> 4, c8 = (chunk & 15) * 8;
            CP_ASYNC16(smem_u32(&Bd[r * BSTR + c8]),
                       W + (size_t)(s * 32 + r) * N + bn + c8);
        }
    };

    stage(0, 0); CP_COMMIT();
    stage(1, 1); CP_COMMIT();
    stage(2, 2); CP_COMMIT();

    for (int s = 0; s < 16; s++) {
        int rem = 15 - s;
        if (rem >= 2)      CP_WAIT(2);
        else if (rem == 1) CP_WAIT(1);
        else               CP_WAIT(0);
        __syncthreads();
        if (s + 3 < 16) { stage(s + 3, (s + 3) & 3); CP_COMMIT(); }

        const __half* Ab = dsm + (s & 3) * GSLOT;
        const __half* Bb = Ab + AHALVES;
        #pragma unroll
        for (int kk = 0; kk < 2; kk++) {
            uint32_t a[2][4];
            #pragma unroll
            for (int mi = 0; mi < 2; mi++) {
                int row = wm + mi * 16 + (lane & 7) + ((lane >> 3) & 1) * 8;
                int kc = kk * 16 + ((lane >> 4) & 1) * 8;
                LDMATRIX_X4(a[mi][0], a[mi][1], a[mi][2], a[mi][3],
                            smem_u32(&Ab[row * ASTR + kc]));
            }
            uint32_t b[8][2];
            #pragma unroll
            for (int bi = 0; bi < 4; bi++) {
                int row = kk * 16 + ((lane >> 3) & 1) * 8 + (lane & 7);
                int col = wn + bi * 16 + (lane >> 4) * 8;
                uint32_t v0, v1, v2, v3;
                LDMATRIX_X4_T(v0, v1, v2, v3, smem_u32(&Bb[row * BSTR + col]));
                b[bi * 2 + 0][0] = v0; b[bi * 2 + 0][1] = v1;
                b[bi * 2 + 1][0] = v2; b[bi * 2 + 1][1] = v3;
            }
            #pragma unroll
            for (int mi = 0; mi < 2; mi++)
                #pragma unroll
                for (int ni = 0; ni < 8; ni++)
                    MMA16816(c[mi][ni], a[mi][0], a[mi][1], a[mi][2], a[mi][3],
                             b[ni][0], b[ni][1]);
        }
    }

    #pragma unroll
    for (int mi = 0; mi < 2; mi++) {
        int r0 = bm + wm + mi * 16 + (lane >> 2);
        #pragma unroll
        for (int ni = 0; ni < 8; ni++) {
            int col = bn + wn + ni * 8 + (lane & 3) * 2;
            float bx = bias[col], by = bias[col + 1];
            float v00 = c[mi][ni][0] + bx, v01 = c[mi][ni][1] + by;
            float v10 = c[mi][ni][2] + bx, v11 = c[mi][ni][3] + by;
            if (HOUT) {
                __half* C = (__half*)Cv;
                *reinterpret_cast<__half2*>(C + (size_t)r0 * N + col) = __floats2half2_rn(v00, v01);
                *reinterpret_cast<__half2*>(C + (size_t)(r0 + 8) * N + col) = __floats2half2_rn(v10, v11);
            } else {
                float* C = (float*)Cv;
                if (R) {
                    const float2 ra = *reinterpret_cast<const float2*>(R + (size_t)r0 * N + col);
                    const float2 rb = *reinterpret_cast<const float2*>(R + (size_t)(r0 + 8) * N + col);
                    v00 += ra.x; v01 += ra.y; v10 += rb.x; v11 += rb.y;
                }
                *reinterpret_cast<float2*>(C + (size_t)r0 * N + col) = make_float2(v00, v01);
                *reinterpret_cast<float2*>(C + (size_t)(r0 + 8) * N + col) = make_float2(v10, v11);
            }
        }
    }
}

// ---------------------------------------------------------------------------
// Kernel 3: HMMA flash attention, 3-slot KV ring.
// Softmax in log2 domain with packed fp16 ex2; l via ones-MMA row sums.
// ---------------------------------------------------------------------------
#define KSTR 72
#define QHALVES (128 * KSTR)
#define KVSLOT  (2 * 64 * KSTR)
#define ATTN_SMEM ((QHALVES + 3 * KVSLOT) * 2)

__global__ __launch_bounds__(256, 2) void attn_hmma(
    const __half* __restrict__ qkv, __half* __restrict__ out)
{
    extern __shared__ __half dsm[];
    __half* Qs = dsm;

    int b = blockIdx.z, h = blockIdx.y, qt = blockIdx.x;
    int tid = threadIdx.x, lane = tid & 31, wid = tid >> 5;

    const __half* base = qkv + (size_t)b * SEQ * C3 + h * HD;

    auto kslot = [&](int slot) -> __half* { return dsm + QHALVES + slot * KVSLOT; };

    auto stageKV = [&](int c, int slot) {
        __half* Kd = kslot(slot);
        __half* Vd = Kd + 64 * KSTR;
        #pragma unroll
        for (int i = 0; i < 2; i++) {
            int chunk = tid + i * 256;
            int r = chunk >> 3, c8 = (chunk & 7) * 8;
            const __half* kg = base + (size_t)(c * 64 + r) * C3 + CC + c8;
            CP_ASYNC16(smem_u32(&Kd[r * KSTR + c8]), kg);
            CP_ASYNC16(smem_u32(&Vd[r * KSTR + c8]), kg + CC);
        }
    };

    #pragma unroll
    for (int i = 0; i < 4; i++) {
        int chunk = tid + i * 256;
        int r = chunk >> 3, c8 = (chunk & 7) * 8;
        CP_ASYNC16(smem_u32(&Qs[r * KSTR + c8]),
                   base + (size_t)(qt * 128 + r) * C3 + c8);
    }
    stageKV(0, 0); CP_COMMIT();
    stageKV(1, 1); CP_COMMIT();

    float o[8][4];
    #pragma unroll
    for (int i = 0; i < 8; i++)
        #pragma unroll
        for (int k = 0; k < 4; k++) o[i][k] = 0.f;
    float cl[4] = {0.f, 0.f, 0.f, 0.f};           // l accumulator (ones-MMA)
    float mrow0 = -1e30f, mrow1 = -1e30f;
    uint32_t qf[4][4];
    const uint32_t ONE2 = 0x3C003C00u;            // half2(1.0, 1.0)

    for (int ch = 0; ch < 16; ch++) {
        if (ch < 15) CP_WAIT(1);
        else         CP_WAIT(0);
        __syncthreads();
        if (ch + 2 < 16) { stageKV(ch + 2, (ch + 2) % 3); CP_COMMIT(); }

        const __half* Kb = kslot(ch % 3);
        const __half* Vb = Kb + 64 * KSTR;

        if (ch == 0) {
            #pragma unroll
            for (int ks = 0; ks < 4; ks++) {
                int row = wid * 16 + (lane & 7) + ((lane >> 3) & 1) * 8;
                int col = ks * 16 + ((lane >> 4) & 1) * 8;
                LDMATRIX_X4(qf[ks][0], qf[ks][1], qf[ks][2], qf[ks][3],
                            smem_u32(&Qs[row * KSTR + col]));
            }
        }

        // ---- S = Q @ K^T ----
        float sacc[8][4];
        #pragma unroll
        for (int j = 0; j < 8; j++)
            #pragma unroll
            for (int k = 0; k < 4; k++) sacc[j][k] = 0.f;

        #pragma unroll
        for (int j = 0; j < 8; j++) {
            uint32_t kf[8];
            uint32_t a0 = smem_u32(&Kb[(8 * j + (lane & 7)) * KSTR + (lane >> 3) * 8]);
            LDMATRIX_X4(kf[0], kf[1], kf[2], kf[3], a0);
            LDMATRIX_X4(kf[4], kf[5], kf[6], kf[7], a0 + 64);
            #pragma unroll
            for (int ks = 0; ks < 4; ks++)
                MMA16816(sacc[j], qf[ks][0], qf[ks][1], qf[ks][2], qf[ks][3],
                         kf[2 * ks], kf[2 * ks + 1]);
        }

        // ---- online softmax in log2 domain: fold log2(e)/64 into scale ----
        const float sc = 1.4426950408889634f / 64.0f;
        #pragma unroll
        for (int j = 0; j < 8; j++)
            #pragma unroll
            for (int k = 0; k < 4; k++) sacc[j][k] *= sc;

        float mx0 = mrow0, mx1 = mrow1;
        #pragma unroll
        for (int j = 0; j < 8; j++) {
            mx0 = fmaxf(mx0, fmaxf(sacc[j][0], sacc[j][1]));
            mx1 = fmaxf(mx1, fmaxf(sacc[j][2], sacc[j][3]));
        }
        mx0 = fmaxf(mx0, __shfl_xor_sync(0xFFFFFFFFu, mx0, 1));
        mx0 = fmaxf(mx0, __shfl_xor_sync(0xFFFFFFFFu, mx0, 2));
        mx1 = fmaxf(mx1, __shfl_xor_sync(0xFFFFFFFFu, mx1, 1));
        mx1 = fmaxf(mx1, __shfl_xor_sync(0xFFFFFFFFu, mx1, 2));

        float corr0 = exp2f(mrow0 - mx0);
        float corr1 = exp2f(mrow1 - mx1);
        mrow0 = mx0; mrow1 = mx1;
        #pragma unroll
        for (int nd = 0; nd < 8; nd++) {
            o[nd][0] *= corr0; o[nd][1] *= corr0;
            o[nd][2] *= corr1; o[nd][3] *= corr1;
        }
        cl[0] *= corr0; cl[2] *= corr1;

        // p = 2^(s - m), computed packed-fp16 (one MUFU per 2 values)
        uint32_t pf[4][4];
        #pragma unroll
        for (int jp = 0; jp < 4; jp++) {
            pf[jp][0] = ex2h2(sacc[2 * jp][0] - mx0, sacc[2 * jp][1] - mx0);
            pf[jp][1] = ex2h2(sacc[2 * jp][2] - mx1, sacc[2 * jp][3] - mx1);
            pf[jp][2] = ex2h2(sacc[2 * jp + 1][0] - mx0, sacc[2 * jp + 1][1] - mx0);
            pf[jp][3] = ex2h2(sacc[2 * jp + 1][2] - mx1, sacc[2 * jp + 1][3] - mx1);
        }

        // ---- O += P @ V ; l += P @ ones ----
        #pragma unroll
        for (int ks = 0; ks < 4; ks++) {
            MMA16816(cl, pf[ks][0], pf[ks][1], pf[ks][2], pf[ks][3], ONE2, ONE2);
            #pragma unroll
            for (int np = 0; np < 4; np++) {
                uint32_t v0, v1, v2, v3;
                int row = 16 * ks + ((lane >> 3) & 1) * 8 + (lane & 7);
                int col = np * 16 + (lane >> 4) * 8;
                LDMATRIX_X4_T(v0, v1, v2, v3, smem_u32(&Vb[row * KSTR + col]));
                MMA16816(o[2 * np], pf[ks][0], pf[ks][1], pf[ks][2], pf[ks][3], v0, v1);
                MMA16816(o[2 * np + 1], pf[ks][0], pf[ks][1], pf[ks][2], pf[ks][3], v2, v3);
            }
        }
    }

    // ---- finalize: cl[0]/cl[2] already hold full row sums ----
    float inv0 = 1.0f / cl[0], inv1 = 1.0f / cl[2];

    int r0 = qt * 128 + wid * 16 + (lane >> 2);
    __half* ob = out + (size_t)b * SEQ * CC + h * HD;
    #pragma unroll
    for (int nd = 0; nd < 8; nd++) {
        int col = nd * 8 + (lane & 3) * 2;
        *reinterpret_cast<__half2*>(ob + (size_t)r0 * CC + col) =
            __floats2half2_rn(o[nd][0] * inv0, o[nd][1] * inv0);
        *reinterpret_cast<__half2*>(ob + (size_t)(r0 + 8) * CC + col) =
            __floats2half2_rn(o[nd][2] * inv1, o[nd][3] * inv1);
    }
}

// ---------------------------------------------------------------------------
// Launch
// ---------------------------------------------------------------------------
extern "C" void kernel_launch(void* const* d_in, const int* in_sizes, int n_in,
                              void* d_out, int out_size)
{
    const float* x        = (const float*)d_in[0];
    const float* gn_scale = (const float*)d_in[1];
    const float* gn_bias  = (const float*)d_in[2];
    const float* w_qkv    = (const float*)d_in[3];
    const float* b_qkv    = (const float*)d_in[4];
    const float* w_out    = (const float*)d_in[5];
    const float* b_out    = (const float*)d_in[6];
    float* out            = (float*)d_out;

    __half* xn;   cudaGetSymbolAddress((void**)&xn,   g_xn_h);
    __half* qkv;  cudaGetSymbolAddress((void**)&qkv,  g_qkv_h);
    __half* attn; cudaGetSymbolAddress((void**)&attn, g_attn_h);
    __half* whq;  cudaGetSymbolAddress((void**)&whq,  g_wh_qkv);
    __half* who;  cudaGetSymbolAddress((void**)&who,  g_wh_out);

    cudaFuncSetAttribute(gemm_hmma<true>,  cudaFuncAttributeMaxDynamicSharedMemorySize, GEMM_SMEM);
    cudaFuncSetAttribute(gemm_hmma<false>, cudaFuncAttributeMaxDynamicSharedMemorySize, GEMM_SMEM);
    cudaFuncSetAttribute(attn_hmma,        cudaFuncAttributeMaxDynamicSharedMemorySize, ATTN_SMEM);

    // 0) weight converts (fp32 -> fp16, layout preserved)
    wconv_kernel<<<(CC * C3 / 4 + 255) / 256, 256>>>(w_qkv, whq, CC * C3);
    wconv_kernel<<<(CC * CC / 4 + 255) / 256, 256>>>(w_out, who, CC * CC);

    // 1) GroupNorm -> fp16
    gn_kernel<<<BB * NG, 256>>>(x, gn_scale, gn_bias, xn);

    // 2) QKV projection (HMMA, fp16 out)
    gemm_hmma<true><<<dim3(C3 / 128, (BB * SEQ) / 128), 256, GEMM_SMEM>>>(xn, whq, b_qkv, nullptr, qkv, C3);

    // 3) Attention (HMMA flash)
    attn_hmma<<<dim3(SEQ / 128, NH, BB), 256, ATTN_SMEM>>>(qkv, attn);

    // 4) Output projection + bias + residual (HMMA, fp32 out)
    gemm_hmma<false><<<dim3(CC / 128, (BB * SEQ) / 128), 256, GEMM_SMEM>>>(attn, who, b_out, x, out, CC);
}

// round 14
// speedup vs baseline: 1.2133x; 1.0170x over previous
#include <cuda_runtime.h>
#include <cuda_fp16.h>
#include <cstdint>

// Problem constants
#define BB 8
#define SEQ 1024
#define CC 512
#define NH 8
#define HD 64
#define NG 32
#define GSZ 16
#define C3 1536

// Scratch
__device__ __half g_xn_h[BB * SEQ * CC];    // normalized x (fp16)
__device__ __half g_qkv_h[BB * SEQ * C3];   // qkv projection (fp16)
__device__ __half g_attn_h[BB * SEQ * CC];  // attention output (fp16)
__device__ __half g_wh_qkv[CC * C3];        // w_qkv [K,N] fp16
__device__ __half g_wh_out[CC * CC];        // w_out [K,N] fp16

// ---------------------------------------------------------------------------
// helpers
// ---------------------------------------------------------------------------
__device__ __forceinline__ uint32_t smem_u32(const void* p) {
    uint32_t a; asm("{ .reg .u64 t; cvta.to.shared.u64 t, %1; cvt.u32.u64 %0, t; }" : "=r"(a) : "l"(p));
    return a;
}
// packed fp16 exp2 of (a, b): one MUFU op for two values
__device__ __forceinline__ uint32_t ex2h2(float a, float b) {
    __half2 h = __floats2half2_rn(a, b);
    uint32_t u = *reinterpret_cast<uint32_t*>(&h);
    uint32_t r; asm("ex2.approx.f16x2 %0, %1;" : "=r"(r) : "r"(u));
    return r;
}

#define CP_ASYNC16(sa, ga) \
    asm volatile("cp.async.cg.shared.global [%0], [%1], 16;" :: "r"(sa), "l"(ga))
#define CP_COMMIT() asm volatile("cp.async.commit_group;")
#define CP_WAIT(n)  asm volatile("cp.async.wait_group %0;" :: "n"(n))

#define LDMATRIX_X4(r0, r1, r2, r3, addr) \
    asm volatile("ldmatrix.sync.aligned.m8n8.x4.shared.b16 {%0,%1,%2,%3}, [%4];" \
        : "=r"(r0), "=r"(r1), "=r"(r2), "=r"(r3) : "r"(addr))

#define LDMATRIX_X4_T(r0, r1, r2, r3, addr) \
    asm volatile("ldmatrix.sync.aligned.m8n8.x4.trans.shared.b16 {%0,%1,%2,%3}, [%4];" \
        : "=r"(r0), "=r"(r1), "=r"(r2), "=r"(r3) : "r"(addr))

#define MMA16816(c, a0, a1, a2, a3, b0, b1) \
    asm volatile("mma.sync.aligned.m16n8k16.row.col.f32.f16.f16.f32 " \
        "{%0,%1,%2,%3}, {%4,%5,%6,%7}, {%8,%9}, {%0,%1,%2,%3};" \
        : "+f"((c)[0]), "+f"((c)[1]), "+f"((c)[2]), "+f"((c)[3]) \
        : "r"(a0), "r"(a1), "r"(a2), "r"(a3), "r"(b0), "r"(b1))

// ---------------------------------------------------------------------------
// Kernel 0: both weight converts in ONE launch (f32 -> f16, layout preserved)
// ---------------------------------------------------------------------------
#define NQKV (CC * C3)
#define NOUT (CC * CC)

__global__ __launch_bounds__(256) void wconv_kernel(
    const float* __restrict__ Wq, __half* __restrict__ Whq,
    const float* __restrict__ Wo, __half* __restrict__ Who)
{
    int i = (blockIdx.x * 256 + threadIdx.x) * 4;
    if (i < NQKV) {
        float4 v = *reinterpret_cast<const float4*>(Wq + i);
        __half2* o = reinterpret_cast<__half2*>(Whq + i);
        o[0] = __floats2half2_rn(v.x, v.y);
        o[1] = __floats2half2_rn(v.z, v.w);
    } else {
        int j = i - NQKV;
        if (j < NOUT) {
            float4 v = *reinterpret_cast<const float4*>(Wo + j);
            __half2* o = reinterpret_cast<__half2*>(Who + j);
            o[0] = __floats2half2_rn(v.x, v.y);
            o[1] = __floats2half2_rn(v.z, v.w);
        }
    }
}

// ---------------------------------------------------------------------------
// Kernel 1: GroupNorm -> fp16. Quad-coalesced.
// ---------------------------------------------------------------------------
__global__ __launch_bounds__(256) void gn_kernel(
    const float* __restrict__ x, const float* __restrict__ gamma,
    const float* __restrict__ beta, __half* __restrict__ xn)
{
    int bg = blockIdx.x;
    int b = bg >> 5, g = bg & 31;
    const float* base = x + (size_t)b * SEQ * CC + g * GSZ;
    int tid = threadIdx.x;
    int q4 = tid & 3;
    int sbase = tid >> 2;

    float sum = 0.f, sq = 0.f;
    #pragma unroll
    for (int i = 0; i < 16; i++) {
        int s = sbase + i * 64;
        float4 v = *reinterpret_cast<const float4*>(base + (size_t)s * CC + q4 * 4);
        sum += v.x + v.y + v.z + v.w;
        sq  += v.x * v.x + v.y * v.y + v.z * v.z + v.w * v.w;
    }
    #pragma unroll
    for (int off = 16; off; off >>= 1) {
        sum += __shfl_xor_sync(0xFFFFFFFFu, sum, off);
        sq  += __shfl_xor_sync(0xFFFFFFFFu, sq, off);
    }
    __shared__ float red[2][8];
    __shared__ float stats[2];
    int wid = tid >> 5, lid = tid & 31;
    if (lid == 0) { red[0][wid] = sum; red[1][wid] = sq; }
    __syncthreads();
    if (tid == 0) {
        float S = 0.f, Q = 0.f;
        #pragma unroll
        for (int w = 0; w < 8; w++) { S += red[0][w]; Q += red[1][w]; }
        float mu = S * (1.f / 16384.f);
        float var = Q * (1.f / 16384.f) - mu * mu;
        stats[0] = mu;
        stats[1] = rsqrtf(var + 1e-6f);
    }
    __syncthreads();
    float mu = stats[0], rstd = stats[1];

    float ga[4], be[4];
    #pragma unroll
    for (int c = 0; c < 4; c++) {
        ga[c] = gamma[g * GSZ + q4 * 4 + c] * rstd;
        be[c] = beta[g * GSZ + q4 * 4 + c];
    }
    __half* obase = xn + (size_t)b * SEQ * CC + g * GSZ;
    #pragma unroll
    for (int i = 0; i < 16; i++) {
        int s = sbase + i * 64;
        float4 v = *reinterpret_cast<const float4*>(base + (size_t)s * CC + q4 * 4);
        float y0 = (v.x - mu) * ga[0] + be[0];
        float y1 = (v.y - mu) * ga[1] + be[1];
        float y2 = (v.z - mu) * ga[2] + be[2];
        float y3 = (v.w - mu) * ga[3] + be[3];
        __half2* q = reinterpret_cast<__half2*>(obase + (size_t)s * CC + q4 * 4);
        q[0] = __floats2half2_rn(y0, y1);
        q[1] = __floats2half2_rn(y2, y3);
    }
}

// ---------------------------------------------------------------------------
// Kernel 2: fp16 HMMA GEMM, BK=32, 4-slot cp.async ring, s-loop unrolled x4
// so slot indices const-fold and smem addressing hoists.
// ---------------------------------------------------------------------------
#define ASTR 40
#define BSTR 136
#define AHALVES (128 * ASTR)
#define BHALVES (32 * BSTR)
#define GSLOT (AHALVES + BHALVES)
#define GEMM_SMEM (4 * GSLOT * 2)

template<bool HOUT>
__global__ __launch_bounds__(256, 2) void gemm_hmma(
    const __half* __restrict__ A, const __half* __restrict__ W,
    const float* __restrict__ bias, const float* __restrict__ R,
    void* __restrict__ Cv, int N)
{
    extern __shared__ __half dsm[];

    int tid = threadIdx.x;
    int lane = tid & 31;
    int wid = tid >> 5;
    int wm = (wid & 3) * 32;
    int wn = (wid >> 2) * 64;
    int bm = blockIdx.y * 128;
    int bn = blockIdx.x * 128;

    float c[2][8][4];
    #pragma unroll
    for (int mi = 0; mi < 2; mi++)
        #pragma unroll
        for (int ni = 0; ni < 8; ni++)
            #pragma unroll
            for (int k = 0; k < 4; k++) c[mi][ni][k] = 0.f;

    auto stage = [&](int s, int slot) {
        __half* Ad = dsm + slot * GSLOT;
        __half* Bd = Ad + AHALVES;
        #pragma unroll
        for (int i = 0; i < 2; i++) {
            int chunk = tid + i * 256;
            int r = chunk >> 2, c8 = (chunk & 3) * 8;
            CP_ASYNC16(smem_u32(&Ad[r * ASTR + c8]),
                       A + (size_t)(bm + r) * 512 + s * 32 + c8);
        }
        #pragma unroll
        for (int i = 0; i < 2; i++) {
            int chunk = tid + i * 256;
            int r = chunk >> 4, c8 = (chunk & 15) * 8;
            CP_ASYNC16(smem_u32(&Bd[r * BSTR + c8]),
                       W + (size_t)(s * 32 + r) * N + bn + c8);
        }
    };

    stage(0, 0); CP_COMMIT();
    stage(1, 1); CP_COMMIT();
    stage(2, 2); CP_COMMIT();

    #pragma unroll 4
    for (int s = 0; s < 16; s++) {
        int rem = 15 - s;
        if (rem >= 2)      CP_WAIT(2);
        else if (rem == 1) CP_WAIT(1);
        else               CP_WAIT(0);
        __syncthreads();
        if (s + 3 < 16) { stage(s + 3, (s + 3) & 3); CP_COMMIT(); }

        const __half* Ab = dsm + (s & 3) * GSLOT;
        const __half* Bb = Ab + AHALVES;
        #pragma unroll
        for (int kk = 0; kk < 2; kk++) {
            uint32_t a[2][4];
            #pragma unroll
            for (int mi = 0; mi < 2; mi++) {
                int row = wm + mi * 16 + (lane & 7) + ((lane >> 3) & 1) * 8;
                int kc = kk * 16 + ((lane >> 4) & 1) * 8;
                LDMATRIX_X4(a[mi][0], a[mi][1], a[mi][2], a[mi][3],
                            smem_u32(&Ab[row * ASTR + kc]));
            }
            uint32_t b[8][2];
            #pragma unroll
            for (int bi = 0; bi < 4; bi++) {
                int row = kk * 16 + ((lane >> 3) & 1) * 8 + (lane & 7);
                int col = wn + bi * 16 + (lane >> 4) * 8;
                uint32_t v0, v1, v2, v3;
                LDMATRIX_X4_T(v0, v1, v2, v3, smem_u32(&Bb[row * BSTR + col]));
                b[bi * 2 + 0][0] = v0; b[bi * 2 + 0][1] = v1;
                b[bi * 2 + 1][0] = v2; b[bi * 2 + 1][1] = v3;
            }
            #pragma unroll
            for (int mi = 0; mi < 2; mi++)
                #pragma unroll
                for (int ni = 0; ni < 8; ni++)
                    MMA16816(c[mi][ni], a[mi][0], a[mi][1], a[mi][2], a[mi][3],
                             b[ni][0], b[ni][1]);
        }
    }

    #pragma unroll
    for (int mi = 0; mi < 2; mi++) {
        int r0 = bm + wm + mi * 16 + (lane >> 2);
        #pragma unroll
        for (int ni = 0; ni < 8; ni++) {
            int col = bn + wn + ni * 8 + (lane & 3) * 2;
            float bx = bias[col], by = bias[col + 1];
            float v00 = c[mi][ni][0] + bx, v01 = c[mi][ni][1] + by;
            float v10 = c[mi][ni][2] + bx, v11 = c[mi][ni][3] + by;
            if (HOUT) {
                __half* C = (__half*)Cv;
                *reinterpret_cast<__half2*>(C + (size_t)r0 * N + col) = __floats2half2_rn(v00, v01);
                *reinterpret_cast<__half2*>(C + (size_t)(r0 + 8) * N + col) = __floats2half2_rn(v10, v11);
            } else {
                float* C = (float*)Cv;
                if (R) {
                    const float2 ra = *reinterpret_cast<const float2*>(R + (size_t)r0 * N + col);
                    const float2 rb = *reinterpret_cast<const float2*>(R + (size_t)(r0 + 8) * N + col);
                    v00 += ra.x; v01 += ra.y; v10 += rb.x; v11 += rb.y;
                }
                *reinterpret_cast<float2*>(C + (size_t)r0 * N + col) = make_float2(v00, v01);
                *reinterpret_cast<float2*>(C + (size_t)(r0 + 8) * N + col) = make_float2(v10, v11);
            }
        }
    }
}

// ---------------------------------------------------------------------------
// Kernel 3: HMMA flash attention, 4-slot KV ring, depth-3 prefetch,
// ch-loop unrolled x4 (slot const-folds). log2-domain packed-fp16 softmax,
// l via ones-MMA.
// ---------------------------------------------------------------------------
#define KSTR 72
#define QHALVES (128 * KSTR)
#define KVSLOT  (2 * 64 * KSTR)     // 9216 halves
#define ATTN_SMEM ((QHALVES + 4 * KVSLOT) * 2)   // 92160 bytes

__global__ __launch_bounds__(256, 2) void attn_hmma(
    const __half* __restrict__ qkv, __half* __restrict__ out)
{
    extern __shared__ __half dsm[];
    __half* Qs = dsm;

    int b = blockIdx.z, h = blockIdx.y, qt = blockIdx.x;
    int tid = threadIdx.x, lane = tid & 31, wid = tid >> 5;

    const __half* base = qkv + (size_t)b * SEQ * C3 + h * HD;

    auto kslot = [&](int slot) -> __half* { return dsm + QHALVES + slot * KVSLOT; };

    auto stageKV = [&](int c, int slot) {
        __half* Kd = kslot(slot);
        __half* Vd = Kd + 64 * KSTR;
        #pragma unroll
        for (int i = 0; i < 2; i++) {
            int chunk = tid + i * 256;
            int r = chunk >> 3, c8 = (chunk & 7) * 8;
            const __half* kg = base + (size_t)(c * 64 + r) * C3 + CC + c8;
            CP_ASYNC16(smem_u32(&Kd[r * KSTR + c8]), kg);
            CP_ASYNC16(smem_u32(&Vd[r * KSTR + c8]), kg + CC);
        }
    };

    #pragma unroll
    for (int i = 0; i < 4; i++) {
        int chunk = tid + i * 256;
        int r = chunk >> 3, c8 = (chunk & 7) * 8;
        CP_ASYNC16(smem_u32(&Qs[r * KSTR + c8]),
                   base + (size_t)(qt * 128 + r) * C3 + c8);
    }
    stageKV(0, 0); CP_COMMIT();
    stageKV(1, 1); CP_COMMIT();
    stageKV(2, 2); CP_COMMIT();

    float o[8][4];
    #pragma unroll
    for (int i = 0; i < 8; i++)
        #pragma unroll
        for (int k = 0; k < 4; k++) o[i][k] = 0.f;
    float cl[4] = {0.f, 0.f, 0.f, 0.f};
    float mrow0 = -1e30f, mrow1 = -1e30f;
    uint32_t qf[4][4];
    const uint32_t ONE2 = 0x3C003C00u;

    #pragma unroll 4
    for (int ch = 0; ch < 16; ch++) {
        int rem = 15 - ch;
        if (rem >= 2)      CP_WAIT(2);
        else if (rem == 1) CP_WAIT(1);
        else               CP_WAIT(0);
        __syncthreads();
        if (ch + 3 < 16) { stageKV(ch + 3, (ch + 3) & 3); CP_COMMIT(); }

        const __half* Kb = kslot(ch & 3);
        const __half* Vb = Kb + 64 * KSTR;

        if (ch == 0) {
            #pragma unroll
            for (int ks = 0; ks < 4; ks++) {
                int row = wid * 16 + (lane & 7) + ((lane >> 3) & 1) * 8;
                int col = ks * 16 + ((lane >> 4) & 1) * 8;
                LDMATRIX_X4(qf[ks][0], qf[ks][1], qf[ks][2], qf[ks][3],
                            smem_u32(&Qs[row * KSTR + col]));
            }
        }

        // ---- S = Q @ K^T ----
        float sacc[8][4];
        #pragma unroll
        for (int j = 0; j < 8; j++)
            #pragma unroll
            for (int k = 0; k < 4; k++) sacc[j][k] = 0.f;

        #pragma unroll
        for (int j = 0; j < 8; j++) {
            uint32_t kf[8];
            uint32_t a0 = smem_u32(&Kb[(8 * j + (lane & 7)) * KSTR + (lane >> 3) * 8]);
            LDMATRIX_X4(kf[0], kf[1], kf[2], kf[3], a0);
            LDMATRIX_X4(kf[4], kf[5], kf[6], kf[7], a0 + 64);
            #pragma unroll
            for (int ks = 0; ks < 4; ks++)
                MMA16816(sacc[j], qf[ks][0], qf[ks][1], qf[ks][2], qf[ks][3],
                         kf[2 * ks], kf[2 * ks + 1]);
        }

        // ---- online softmax (log2 domain, log2e/64 folded) ----
        const float sc = 1.4426950408889634f / 64.0f;
        #pragma unroll
        for (int j = 0; j < 8; j++)
            #pragma unroll
            for (int k = 0; k < 4; k++) sacc[j][k] *= sc;

        float mx0 = mrow0, mx1 = mrow1;
        #pragma unroll
        for (int j = 0; j < 8; j++) {
            mx0 = fmaxf(mx0, fmaxf(sacc[j][0], sacc[j][1]));
            mx1 = fmaxf(mx1, fmaxf(sacc[j][2], sacc[j][3]));
        }
        mx0 = fmaxf(mx0, __shfl_xor_sync(0xFFFFFFFFu, mx0, 1));
        mx0 = fmaxf(mx0, __shfl_xor_sync(0xFFFFFFFFu, mx0, 2));
        mx1 = fmaxf(mx1, __shfl_xor_sync(0xFFFFFFFFu, mx1, 1));
        mx1 = fmaxf(mx1, __shfl_xor_sync(0xFFFFFFFFu, mx1, 2));

        float corr0 = exp2f(mrow0 - mx0);
        float corr1 = exp2f(mrow1 - mx1);
        mrow0 = mx0; mrow1 = mx1;
        #pragma unroll
        for (int nd = 0; nd < 8; nd++) {
            o[nd][0] *= corr0; o[nd][1] *= corr0;
            o[nd][2] *= corr1; o[nd][3] *= corr1;
        }
        cl[0] *= corr0; cl[2] *= corr1;

        uint32_t pf[4][4];
        #pragma unroll
        for (int jp = 0; jp < 4; jp++) {
            pf[jp][0] = ex2h2(sacc[2 * jp][0] - mx0, sacc[2 * jp][1] - mx0);
            pf[jp][1] = ex2h2(sacc[2 * jp][2] - mx1, sacc[2 * jp][3] - mx1);
            pf[jp][2] = ex2h2(sacc[2 * jp + 1][0] - mx0, sacc[2 * jp + 1][1] - mx0);
            pf[jp][3] = ex2h2(sacc[2 * jp + 1][2] - mx1, sacc[2 * jp + 1][3] - mx1);
        }

        // ---- O += P @ V ; l += P @ ones ----
        #pragma unroll
        for (int ks = 0; ks < 4; ks++) {
            MMA16816(cl, pf[ks][0], pf[ks][1], pf[ks][2], pf[ks][3], ONE2, ONE2);
            #pragma unroll
            for (int np = 0; np < 4; np++) {
                uint32_t v0, v1, v2, v3;
                int row = 16 * ks + ((lane >> 3) & 1) * 8 + (lane & 7);
                int col = np * 16 + (lane >> 4) * 8;
                LDMATRIX_X4_T(v0, v1, v2, v3, smem_u32(&Vb[row * KSTR + col]));
                MMA16816(o[2 * np], pf[ks][0], pf[ks][1], pf[ks][2], pf[ks][3], v0, v1);
                MMA16816(o[2 * np + 1], pf[ks][0], pf[ks][1], pf[ks][2], pf[ks][3], v2, v3);
            }
        }
    }

    // ---- finalize ----
    float inv0 = 1.0f / cl[0], inv1 = 1.0f / cl[2];

    int r0 = qt * 128 + wid * 16 + (lane >> 2);
    __half* ob = out + (size_t)b * SEQ * CC + h * HD;
    #pragma unroll
    for (int nd = 0; nd < 8; nd++) {
        int col = nd * 8 + (lane & 3) * 2;
        *reinterpret_cast<__half2*>(ob + (size_t)r0 * CC + col) =
            __floats2half2_rn(o[nd][0] * inv0, o[nd][1] * inv0);
        *reinterpret_cast<__half2*>(ob + (size_t)(r0 + 8) * CC + col) =
            __floats2half2_rn(o[nd][2] * inv1, o[nd][3] * inv1);
    }
}

// ---------------------------------------------------------------------------
// Launch
// ---------------------------------------------------------------------------
extern "C" void kernel_launch(void* const* d_in, const int* in_sizes, int n_in,
                              void* d_out, int out_size)
{
    const float* x        = (const float*)d_in[0];
    const float* gn_scale = (const float*)d_in[1];
    const float* gn_bias  = (const float*)d_in[2];
    const float* w_qkv    = (const float*)d_in[3];
    const float* b_qkv    = (const float*)d_in[4];
    const float* w_out    = (const float*)d_in[5];
    const float* b_out    = (const float*)d_in[6];
    float* out            = (float*)d_out;

    __half* xn;   cudaGetSymbolAddress((void**)&xn,   g_xn_h);
    __half* qkv;  cudaGetSymbolAddress((void**)&qkv,  g_qkv_h);
    __half* attn; cudaGetSymbolAddress((void**)&attn, g_attn_h);
    __half* whq;  cudaGetSymbolAddress((void**)&whq,  g_wh_qkv);
    __half* who;  cudaGetSymbolAddress((void**)&who,  g_wh_out);

    cudaFuncSetAttribute(gemm_hmma<true>,  cudaFuncAttributeMaxDynamicSharedMemorySize, GEMM_SMEM);
    cudaFuncSetAttribute(gemm_hmma<false>, cudaFuncAttributeMaxDynamicSharedMemorySize, GEMM_SMEM);
    cudaFuncSetAttribute(attn_hmma,        cudaFuncAttributeMaxDynamicSharedMemorySize, ATTN_SMEM);

    // 0) weight converts (single launch covering both arrays)
    wconv_kernel<<<((NQKV + NOUT) / 4 + 255) / 256, 256>>>(w_qkv, whq, w_out, who);

    // 1) GroupNorm -> fp16
    gn_kernel<<<BB * NG, 256>>>(x, gn_scale, gn_bias, xn);

    // 2) QKV projection (HMMA, fp16 out)
    gemm_hmma<true><<<dim3(C3 / 128, (BB * SEQ) / 128), 256, GEMM_SMEM>>>(xn, whq, b_qkv, nullptr, qkv, C3);

    // 3) Attention (HMMA flash)
    attn_hmma<<<dim3(SEQ / 128, NH, BB), 256, ATTN_SMEM>>>(qkv, attn);

    // 4) Output projection + bias + residual (HMMA, fp32 out)
    gemm_hmma<false><<<dim3(CC / 128, (BB * SEQ) / 128), 256, GEMM_SMEM>>>(attn, who, b_out, x, out, CC);
}

// round 15
// speedup vs baseline: 1.2974x; 1.0693x over previous
#include <cuda_runtime.h>
#include <cuda_fp16.h>
#include <cstdint>

// Problem constants
#define BB 8
#define SEQ 1024
#define CC 512
#define NH 8
#define HD 64
#define NG 32
#define GSZ 16
#define C3 1536

// Scratch
__device__ __half g_xn_h[BB * SEQ * CC];    // normalized x (fp16)
__device__ __half g_qkv_h[BB * SEQ * C3];   // qkv projection (fp16)
__device__ __half g_attn_h[BB * SEQ * CC];  // attention output (fp16)
__device__ __half g_wh_qkv[CC * C3];        // w_qkv [K,N] fp16
__device__ __half g_wh_out[CC * CC];        // w_out [K,N] fp16

// ---------------------------------------------------------------------------
// helpers
// ---------------------------------------------------------------------------
__device__ __forceinline__ uint32_t smem_u32(const void* p) {
    uint32_t a; asm("{ .reg .u64 t; cvta.to.shared.u64 t, %1; cvt.u32.u64 %0, t; }" : "=r"(a) : "l"(p));
    return a;
}
// packed fp16 exp2 of (a, b): one MUFU op for two values
__device__ __forceinline__ uint32_t ex2h2(float a, float b) {
    __half2 h = __floats2half2_rn(a, b);
    uint32_t u = *reinterpret_cast<uint32_t*>(&h);
    uint32_t r; asm("ex2.approx.f16x2 %0, %1;" : "=r"(r) : "r"(u));
    return r;
}

#define CP_ASYNC16(sa, ga) \
    asm volatile("cp.async.cg.shared.global [%0], [%1], 16;" :: "r"(sa), "l"(ga))
#define CP_COMMIT() asm volatile("cp.async.commit_group;")
#define CP_WAIT(n)  asm volatile("cp.async.wait_group %0;" :: "n"(n))

#define LDMATRIX_X4(r0, r1, r2, r3, addr) \
    asm volatile("ldmatrix.sync.aligned.m8n8.x4.shared.b16 {%0,%1,%2,%3}, [%4];" \
        : "=r"(r0), "=r"(r1), "=r"(r2), "=r"(r3) : "r"(addr))

#define LDMATRIX_X4_T(r0, r1, r2, r3, addr) \
    asm volatile("ldmatrix.sync.aligned.m8n8.x4.trans.shared.b16 {%0,%1,%2,%3}, [%4];" \
        : "=r"(r0), "=r"(r1), "=r"(r2), "=r"(r3) : "r"(addr))

#define MMA16816(c, a0, a1, a2, a3, b0, b1) \
    asm volatile("mma.sync.aligned.m16n8k16.row.col.f32.f16.f16.f32 " \
        "{%0,%1,%2,%3}, {%4,%5,%6,%7}, {%8,%9}, {%0,%1,%2,%3};" \
        : "+f"((c)[0]), "+f"((c)[1]), "+f"((c)[2]), "+f"((c)[3]) \
        : "r"(a0), "r"(a1), "r"(a2), "r"(a3), "r"(b0), "r"(b1))

// ---------------------------------------------------------------------------
// Kernel 0: both weight converts in ONE launch (f32 -> f16, layout preserved)
// ---------------------------------------------------------------------------
#define NQKV (CC * C3)
#define NOUT (CC * CC)

__global__ __launch_bounds__(256) void wconv_kernel(
    const float* __restrict__ Wq, __half* __restrict__ Whq,
    const float* __restrict__ Wo, __half* __restrict__ Who)
{
    int i = (blockIdx.x * 256 + threadIdx.x) * 4;
    if (i < NQKV) {
        float4 v = *reinterpret_cast<const float4*>(Wq + i);
        __half2* o = reinterpret_cast<__half2*>(Whq + i);
        o[0] = __floats2half2_rn(v.x, v.y);
        o[1] = __floats2half2_rn(v.z, v.w);
    } else {
        int j = i - NQKV;
        if (j < NOUT) {
            float4 v = *reinterpret_cast<const float4*>(Wo + j);
            __half2* o = reinterpret_cast<__half2*>(Who + j);
            o[0] = __floats2half2_rn(v.x, v.y);
            o[1] = __floats2half2_rn(v.z, v.w);
        }
    }
}

// ---------------------------------------------------------------------------
// Kernel 1: GroupNorm -> fp16. Quad-coalesced.
// ---------------------------------------------------------------------------
__global__ __launch_bounds__(256) void gn_kernel(
    const float* __restrict__ x, const float* __restrict__ gamma,
    const float* __restrict__ beta, __half* __restrict__ xn)
{
    int bg = blockIdx.x;
    int b = bg >> 5, g = bg & 31;
    const float* base = x + (size_t)b * SEQ * CC + g * GSZ;
    int tid = threadIdx.x;
    int q4 = tid & 3;
    int sbase = tid >> 2;

    float sum = 0.f, sq = 0.f;
    #pragma unroll
    for (int i = 0; i < 16; i++) {
        int s = sbase + i * 64;
        float4 v = *reinterpret_cast<const float4*>(base + (size_t)s * CC + q4 * 4);
        sum += v.x + v.y + v.z + v.w;
        sq  += v.x * v.x + v.y * v.y + v.z * v.z + v.w * v.w;
    }
    #pragma unroll
    for (int off = 16; off; off >>= 1) {
        sum += __shfl_xor_sync(0xFFFFFFFFu, sum, off);
        sq  += __shfl_xor_sync(0xFFFFFFFFu, sq, off);
    }
    __shared__ float red[2][8];
    __shared__ float stats[2];
    int wid = tid >> 5, lid = tid & 31;
    if (lid == 0) { red[0][wid] = sum; red[1][wid] = sq; }
    __syncthreads();
    if (tid == 0) {
        float S = 0.f, Q = 0.f;
        #pragma unroll
        for (int w = 0; w < 8; w++) { S += red[0][w]; Q += red[1][w]; }
        float mu = S * (1.f / 16384.f);
        float var = Q * (1.f / 16384.f) - mu * mu;
        stats[0] = mu;
        stats[1] = rsqrtf(var + 1e-6f);
    }
    __syncthreads();
    float mu = stats[0], rstd = stats[1];

    float ga[4], be[4];
    #pragma unroll
    for (int c = 0; c < 4; c++) {
        ga[c] = gamma[g * GSZ + q4 * 4 + c] * rstd;
        be[c] = beta[g * GSZ + q4 * 4 + c];
    }
    __half* obase = xn + (size_t)b * SEQ * CC + g * GSZ;
    #pragma unroll
    for (int i = 0; i < 16; i++) {
        int s = sbase + i * 64;
        float4 v = *reinterpret_cast<const float4*>(base + (size_t)s * CC + q4 * 4);
        float y0 = (v.x - mu) * ga[0] + be[0];
        float y1 = (v.y - mu) * ga[1] + be[1];
        float y2 = (v.z - mu) * ga[2] + be[2];
        float y3 = (v.w - mu) * ga[3] + be[3];
        __half2* q = reinterpret_cast<__half2*>(obase + (size_t)s * CC + q4 * 4);
        q[0] = __floats2half2_rn(y0, y1);
        q[1] = __floats2half2_rn(y2, y3);
    }
}

// ---------------------------------------------------------------------------
// Kernel 2: fp16 HMMA GEMM. Tile 64(M)x128(N), BK=32, 128 threads (4 warps,
// warp tile 32x64), 4-slot cp.async ring, 3 CTAs/SM.
// ---------------------------------------------------------------------------
#define ASTR 40
#define BSTR 136
#define AHALVES (64 * ASTR)         // 2560
#define BHALVES (32 * BSTR)         // 4352
#define GSLOT (AHALVES + BHALVES)   // 6912 halves
#define GEMM_SMEM (4 * GSLOT * 2)   // 55296 bytes

template<bool HOUT>
__global__ __launch_bounds__(128, 3) void gemm_hmma(
    const __half* __restrict__ A, const __half* __restrict__ W,
    const float* __restrict__ bias, const float* __restrict__ R,
    void* __restrict__ Cv, int N)
{
    extern __shared__ __half dsm[];

    int tid = threadIdx.x;
    int lane = tid & 31;
    int wid = tid >> 5;               // 0..3
    int wm = (wid & 1) * 32;
    int wn = (wid >> 1) * 64;
    int bm = blockIdx.y * 64;
    int bn = blockIdx.x * 128;

    float c[2][8][4];
    #pragma unroll
    for (int mi = 0; mi < 2; mi++)
        #pragma unroll
        for (int ni = 0; ni < 8; ni++)
            #pragma unroll
            for (int k = 0; k < 4; k++) c[mi][ni][k] = 0.f;

    // stage s (k-chunk of 32): A 64x32, B(W) 32x128
    auto stage = [&](int s, int slot) {
        __half* Ad = dsm + slot * GSLOT;
        __half* Bd = Ad + AHALVES;
        // A: 64 rows x 4 chunks(16B) = 256 chunks, 2/thread
        #pragma unroll
        for (int i = 0; i < 2; i++) {
            int chunk = tid + i * 128;
            int r = chunk >> 2, c8 = (chunk & 3) * 8;
            CP_ASYNC16(smem_u32(&Ad[r * ASTR + c8]),
                       A + (size_t)(bm + r) * 512 + s * 32 + c8);
        }
        // B: 32 rows(k) x 16 chunks(n,16B) = 512 chunks, 4/thread
        #pragma unroll
        for (int i = 0; i < 4; i++) {
            int chunk = tid + i * 128;
            int r = chunk >> 4, c8 = (chunk & 15) * 8;
            CP_ASYNC16(smem_u32(&Bd[r * BSTR + c8]),
                       W + (size_t)(s * 32 + r) * N + bn + c8);
        }
    };

    stage(0, 0); CP_COMMIT();
    stage(1, 1); CP_COMMIT();
    stage(2, 2); CP_COMMIT();

    #pragma unroll 4
    for (int s = 0; s < 16; s++) {
        int rem = 15 - s;
        if (rem >= 2)      CP_WAIT(2);
        else if (rem == 1) CP_WAIT(1);
        else               CP_WAIT(0);
        __syncthreads();
        if (s + 3 < 16) { stage(s + 3, (s + 3) & 3); CP_COMMIT(); }

        const __half* Ab = dsm + (s & 3) * GSLOT;
        const __half* Bb = Ab + AHALVES;
        #pragma unroll
        for (int kk = 0; kk < 2; kk++) {
            uint32_t a[2][4];
            #pragma unroll
            for (int mi = 0; mi < 2; mi++) {
                int row = wm + mi * 16 + (lane & 7) + ((lane >> 3) & 1) * 8;
                int kc = kk * 16 + ((lane >> 4) & 1) * 8;
                LDMATRIX_X4(a[mi][0], a[mi][1], a[mi][2], a[mi][3],
                            smem_u32(&Ab[row * ASTR + kc]));
            }
            uint32_t b[8][2];
            #pragma unroll
            for (int bi = 0; bi < 4; bi++) {
                int row = kk * 16 + ((lane >> 3) & 1) * 8 + (lane & 7);
                int col = wn + bi * 16 + (lane >> 4) * 8;
                uint32_t v0, v1, v2, v3;
                LDMATRIX_X4_T(v0, v1, v2, v3, smem_u32(&Bb[row * BSTR + col]));
                b[bi * 2 + 0][0] = v0; b[bi * 2 + 0][1] = v1;
                b[bi * 2 + 1][0] = v2; b[bi * 2 + 1][1] = v3;
            }
            #pragma unroll
            for (int mi = 0; mi < 2; mi++)
                #pragma unroll
                for (int ni = 0; ni < 8; ni++)
                    MMA16816(c[mi][ni], a[mi][0], a[mi][1], a[mi][2], a[mi][3],
                             b[ni][0], b[ni][1]);
        }
    }

    #pragma unroll
    for (int mi = 0; mi < 2; mi++) {
        int r0 = bm + wm + mi * 16 + (lane >> 2);
        #pragma unroll
        for (int ni = 0; ni < 8; ni++) {
            int col = bn + wn + ni * 8 + (lane & 3) * 2;
            float bx = bias[col], by = bias[col + 1];
            float v00 = c[mi][ni][0] + bx, v01 = c[mi][ni][1] + by;
            float v10 = c[mi][ni][2] + bx, v11 = c[mi][ni][3] + by;
            if (HOUT) {
                __half* C = (__half*)Cv;
                *reinterpret_cast<__half2*>(C + (size_t)r0 * N + col) = __floats2half2_rn(v00, v01);
                *reinterpret_cast<__half2*>(C + (size_t)(r0 + 8) * N + col) = __floats2half2_rn(v10, v11);
            } else {
                float* C = (float*)Cv;
                if (R) {
                    const float2 ra = *reinterpret_cast<const float2*>(R + (size_t)r0 * N + col);
                    const float2 rb = *reinterpret_cast<const float2*>(R + (size_t)(r0 + 8) * N + col);
                    v00 += ra.x; v01 += ra.y; v10 += rb.x; v11 += rb.y;
                }
                *reinterpret_cast<float2*>(C + (size_t)r0 * N + col) = make_float2(v00, v01);
                *reinterpret_cast<float2*>(C + (size_t)(r0 + 8) * N + col) = make_float2(v10, v11);
            }
        }
    }
}

// ---------------------------------------------------------------------------
// Kernel 3: HMMA flash attention. 64 q-rows per CTA, 128 threads (4 warps x
// 16 rows), 3-slot KV ring, 3 CTAs/SM. log2-domain packed-fp16 softmax,
// l via ones-MMA.
// ---------------------------------------------------------------------------
#define KSTR 72
#define AQHALVES (64 * KSTR)        // 4608
#define KVSLOT  (2 * 64 * KSTR)     // 9216 halves
#define ATTN_SMEM ((AQHALVES + 3 * KVSLOT) * 2)   // 64512 bytes

__global__ __launch_bounds__(128, 3) void attn_hmma(
    const __half* __restrict__ qkv, __half* __restrict__ out)
{
    extern __shared__ __half dsm[];
    __half* Qs = dsm;

    int b = blockIdx.z, h = blockIdx.y, qt = blockIdx.x;
    int tid = threadIdx.x, lane = tid & 31, wid = tid >> 5;

    const __half* base = qkv + (size_t)b * SEQ * C3 + h * HD;

    auto kslot = [&](int slot) -> __half* { return dsm + AQHALVES + slot * KVSLOT; };

    auto stageKV = [&](int c, int slot) {
        __half* Kd = kslot(slot);
        __half* Vd = Kd + 64 * KSTR;
        #pragma unroll
        for (int i = 0; i < 4; i++) {
            int chunk = tid + i * 128;
            int r = chunk >> 3, c8 = (chunk & 7) * 8;
            const __half* kg = base + (size_t)(c * 64 + r) * C3 + CC + c8;
            CP_ASYNC16(smem_u32(&Kd[r * KSTR + c8]), kg);
            CP_ASYNC16(smem_u32(&Vd[r * KSTR + c8]), kg + CC);
        }
    };

    // stage Q (64 rows x 64 halves = 512 x 16B chunks, 4/thread)
    #pragma unroll
    for (int i = 0; i < 4; i++) {
        int chunk = tid + i * 128;
        int r = chunk >> 3, c8 = (chunk & 7) * 8;
        CP_ASYNC16(smem_u32(&Qs[r * KSTR + c8]),
                   base + (size_t)(qt * 64 + r) * C3 + c8);
    }
    stageKV(0, 0); CP_COMMIT();
    stageKV(1, 1); CP_COMMIT();

    float o[8][4];
    #pragma unroll
    for (int i = 0; i < 8; i++)
        #pragma unroll
        for (int k = 0; k < 4; k++) o[i][k] = 0.f;
    float cl[4] = {0.f, 0.f, 0.f, 0.f};
    float mrow0 = -1e30f, mrow1 = -1e30f;
    uint32_t qf[4][4];
    const uint32_t ONE2 = 0x3C003C00u;

    for (int ch = 0; ch < 16; ch++) {
        if (ch < 15) CP_WAIT(1);
        else         CP_WAIT(0);
        __syncthreads();
        if (ch + 2 < 16) { stageKV(ch + 2, (ch + 2) % 3); CP_COMMIT(); }

        const __half* Kb = kslot(ch % 3);
        const __half* Vb = Kb + 64 * KSTR;

        if (ch == 0) {
            #pragma unroll
            for (int ks = 0; ks < 4; ks++) {
                int row = wid * 16 + (lane & 7) + ((lane >> 3) & 1) * 8;
                int col = ks * 16 + ((lane >> 4) & 1) * 8;
                LDMATRIX_X4(qf[ks][0], qf[ks][1], qf[ks][2], qf[ks][3],
                            smem_u32(&Qs[row * KSTR + col]));
            }
        }

        // ---- S = Q @ K^T ----
        float sacc[8][4];
        #pragma unroll
        for (int j = 0; j < 8; j++)
            #pragma unroll
            for (int k = 0; k < 4; k++) sacc[j][k] = 0.f;

        #pragma unroll
        for (int j = 0; j < 8; j++) {
            uint32_t kf[8];
            uint32_t a0 = smem_u32(&Kb[(8 * j + (lane & 7)) * KSTR + (lane >> 3) * 8]);
            LDMATRIX_X4(kf[0], kf[1], kf[2], kf[3], a0);
            LDMATRIX_X4(kf[4], kf[5], kf[6], kf[7], a0 + 64);
            #pragma unroll
            for (int ks = 0; ks < 4; ks++)
                MMA16816(sacc[j], qf[ks][0], qf[ks][1], qf[ks][2], qf[ks][3],
                         kf[2 * ks], kf[2 * ks + 1]);
        }

        // ---- online softmax (log2 domain, log2e/64 folded) ----
        const float sc = 1.4426950408889634f / 64.0f;
        #pragma unroll
        for (int j = 0; j < 8; j++)
            #pragma unroll
            for (int k = 0; k < 4; k++) sacc[j][k] *= sc;

        float mx0 = mrow0, mx1 = mrow1;
        #pragma unroll
        for (int j = 0; j < 8; j++) {
            mx0 = fmaxf(mx0, fmaxf(sacc[j][0], sacc[j][1]));
            mx1 = fmaxf(mx1, fmaxf(sacc[j][2], sacc[j][3]));
        }
        mx0 = fmaxf(mx0, __shfl_xor_sync(0xFFFFFFFFu, mx0, 1));
        mx0 = fmaxf(mx0, __shfl_xor_sync(0xFFFFFFFFu, mx0, 2));
        mx1 = fmaxf(mx1, __shfl_xor_sync(0xFFFFFFFFu, mx1, 1));
        mx1 = fmaxf(mx1, __shfl_xor_sync(0xFFFFFFFFu, mx1, 2));

        float corr0 = exp2f(mrow0 - mx0);
        float corr1 = exp2f(mrow1 - mx1);
        mrow0 = mx0; mrow1 = mx1;
        #pragma unroll
        for (int nd = 0; nd < 8; nd++) {
            o[nd][0] *= corr0; o[nd][1] *= corr0;
            o[nd][2] *= corr1; o[nd][3] *= corr1;
        }
        cl[0] *= corr0; cl[2] *= corr1;

        uint32_t pf[4][4];
        #pragma unroll
        for (int jp = 0; jp < 4; jp++) {
            pf[jp][0] = ex2h2(sacc[2 * jp][0] - mx0, sacc[2 * jp][1] - mx0);
            pf[jp][1] = ex2h2(sacc[2 * jp][2] - mx1, sacc[2 * jp][3] - mx1);
            pf[jp][2] = ex2h2(sacc[2 * jp + 1][0] - mx0, sacc[2 * jp + 1][1] - mx0);
            pf[jp][3] = ex2h2(sacc[2 * jp + 1][2] - mx1, sacc[2 * jp + 1][3] - mx1);
        }

        // ---- O += P @ V ; l += P @ ones ----
        #pragma unroll
        for (int ks = 0; ks < 4; ks++) {
            MMA16816(cl, pf[ks][0], pf[ks][1], pf[ks][2], pf[ks][3], ONE2, ONE2);
            #pragma unroll
            for (int np = 0; np < 4; np++) {
                uint32_t v0, v1, v2, v3;
                int row = 16 * ks + ((lane >> 3) & 1) * 8 + (lane & 7);
                int col = np * 16 + (lane >> 4) * 8;
                LDMATRIX_X4_T(v0, v1, v2, v3, smem_u32(&Vb[row * KSTR + col]));
                MMA16816(o[2 * np], pf[ks][0], pf[ks][1], pf[ks][2], pf[ks][3], v0, v1);
                MMA16816(o[2 * np + 1], pf[ks][0], pf[ks][1], pf[ks][2], pf[ks][3], v2, v3);
            }
        }
    }

    // ---- finalize ----
    float inv0 = 1.0f / cl[0], inv1 = 1.0f / cl[2];

    int r0 = qt * 64 + wid * 16 + (lane >> 2);
    __half* ob = out + (size_t)b * SEQ * CC + h * HD;
    #pragma unroll
    for (int nd = 0; nd < 8; nd++) {
        int col = nd * 8 + (lane & 3) * 2;
        *reinterpret_cast<__half2*>(ob + (size_t)r0 * CC + col) =
            __floats2half2_rn(o[nd][0] * inv0, o[nd][1] * inv0);
        *reinterpret_cast<__half2*>(ob + (size_t)(r0 + 8) * CC + col) =
            __floats2half2_rn(o[nd][2] * inv1, o[nd][3] * inv1);
    }
}

// ---------------------------------------------------------------------------
// Launch
// ---------------------------------------------------------------------------
extern "C" void kernel_launch(void* const* d_in, const int* in_sizes, int n_in,
                              void* d_out, int out_size)
{
    const float* x        = (const float*)d_in[0];
    const float* gn_scale = (const float*)d_in[1];
    const float* gn_bias  = (const float*)d_in[2];
    const float* w_qkv    = (const float*)d_in[3];
    const float* b_qkv    = (const float*)d_in[4];
    const float* w_out    = (const float*)d_in[5];
    const float* b_out    = (const float*)d_in[6];
    float* out            = (float*)d_out;

    __half* xn;   cudaGetSymbolAddress((void**)&xn,   g_xn_h);
    __half* qkv;  cudaGetSymbolAddress((void**)&qkv,  g_qkv_h);
    __half* attn; cudaGetSymbolAddress((void**)&attn, g_attn_h);
    __half* whq;  cudaGetSymbolAddress((void**)&whq,  g_wh_qkv);
    __half* who;  cudaGetSymbolAddress((void**)&who,  g_wh_out);

    cudaFuncSetAttribute(gemm_hmma<true>,  cudaFuncAttributeMaxDynamicSharedMemorySize, GEMM_SMEM);
    cudaFuncSetAttribute(gemm_hmma<false>, cudaFuncAttributeMaxDynamicSharedMemorySize, GEMM_SMEM);
    cudaFuncSetAttribute(attn_hmma,        cudaFuncAttributeMaxDynamicSharedMemorySize, ATTN_SMEM);

    // 0) weight converts (single launch covering both arrays)
    wconv_kernel<<<((NQKV + NOUT) / 4 + 255) / 256, 256>>>(w_qkv, whq, w_out, who);

    // 1) GroupNorm -> fp16
    gn_kernel<<<BB * NG, 256>>>(x, gn_scale, gn_bias, xn);

    // 2) QKV projection (HMMA, fp16 out): tiles 64x128, grid (12, 128)
    gemm_hmma<true><<<dim3(C3 / 128, (BB * SEQ) / 64), 128, GEMM_SMEM>>>(xn, whq, b_qkv, nullptr, qkv, C3);

    // 3) Attention (HMMA flash): 64 q-rows per CTA, grid (16, 8, 8)
    attn_hmma<<<dim3(SEQ / 64, NH, BB), 128, ATTN_SMEM>>>(qkv, attn);

    // 4) Output projection + bias + residual (HMMA, fp32 out): grid (4, 128)
    gemm_hmma<false><<<dim3(CC / 128, (BB * SEQ) / 64), 128, GEMM_SMEM>>>(attn, who, b_out, x, out, CC);
}